// round 8
// baseline (speedup 1.0000x reference)
#include <cuda_runtime.h>
#include <math.h>
#include <stdint.h>

// Problem constants
#define D_DIM   1024
#define S_LEN   4096
#define B_SZ    2
#define A_DIM   64
#define DI_DIM  4096
#define TOPK    32
#define NROWS   (B_SZ * S_LEN)                 // 8192
#define ROWELEMS ((long)NROWS * D_DIM)         // 8,388,608

#define NEG_INF (-3.402823466e38f)

// ---------------------------------------------------------------------------
// Scratch layout (floats)
// ---------------------------------------------------------------------------
#define BUF  8388608L
static const long O_HHI    = 0L  * BUF;
static const long O_HLO    = 1L  * BUF;
static const long O_XVHI   = 2L  * BUF;   // xv / xk2
static const long O_XVLO   = 3L  * BUF;
static const long O_XRHI   = 4L  * BUF;   // xr / xr2
static const long O_XRLO   = 5L  * BUF;
static const long O_VTM    = 6L  * BUF;
static const long O_RTM    = 7L  * BUF;
static const long O_VV     = 8L  * BUF;   // sa V; later reused as rkv_lo
static const long O_ATTNHI = 9L  * BUF;
static const long O_ATTNLO = 10L * BUF;
static const long O_RKVHI  = 11L * BUF;
static const long O_X2     = 12L * BUF;
static const long O_R2     = 13L * BUF;
static const long O_QHI    = 14L * BUF;                    // 524288 each
static const long O_QLO    = O_QHI + 524288L;
static const long O_KHI    = O_QLO + 524288L;
static const long O_KLO    = O_KHI + 524288L;
static const long O_SC     = O_KLO + 524288L;              // 33554432
static const long O_KCHI   = O_SC   + 33554432L;
static const long O_KCLO   = O_KCHI + 33554432L;
static const long O_W      = O_KCLO + 33554432L;
// weight splits (hi, lo pairs)
#define WDD 1048576L
static const long O_WTMV = O_W;                 // tm_value
static const long O_WTMR = O_WTMV + 2*WDD;      // tm_recept
static const long O_WSAV = O_WTMR + 2*WDD;      // sa_v
static const long O_WSAO = O_WSAV + 2*WDD;      // sa_o
static const long O_WTMO = O_WSAO + 2*WDD;      // tm_out
static const long O_WCMR = O_WTMO + 2*WDD;      // cm_recept
static const long O_WCMK = O_WCMR + 2*WDD;                 // 4194304 each
static const long O_WCMV = O_WCMK + 2*4194304L;
static const long O_WQK  = O_WCMV + 2*4194304L;            // 131072 each
// total = O_WQK + 2*131072 = 249,823,232 floats

__device__ __align__(16) float g_scratch[249823232];

// ===========================================================================
// helpers
// ===========================================================================
__device__ __forceinline__ uint32_t smem_u32(const void* p) {
    uint32_t a;
    asm("{ .reg .u64 t; cvta.to.shared.u64 t, %1; cvt.u32.u64 %0, t; }"
        : "=r"(a) : "l"(p));
    return a;
}
__device__ __forceinline__ uint32_t f2tf32(float x) {
    uint32_t r;
    asm("cvt.rna.tf32.f32 %0, %1;" : "=r"(r) : "f"(x));
    return r;
}
__device__ __forceinline__ void fsplit(float v, float& hi, float& lo) {
    hi = __uint_as_float(f2tf32(v));
    lo = __uint_as_float(f2tf32(v - hi));
}
__device__ __forceinline__ float sigmoidf_(float x) { return 1.f / (1.f + expf(-x)); }

__device__ __forceinline__ void cp16(uint32_t s, const void* g) {
    asm volatile("cp.async.cg.shared.global [%0], [%1], 16;" :: "r"(s), "l"(g));
}
__device__ __forceinline__ void mma1688(float* c, const uint32_t* a, const uint32_t* b) {
    asm volatile(
        "mma.sync.aligned.m16n8k8.row.col.f32.tf32.tf32.f32 "
        "{%0,%1,%2,%3}, {%4,%5,%6,%7}, {%8,%9}, {%0,%1,%2,%3};"
        : "+f"(c[0]), "+f"(c[1]), "+f"(c[2]), "+f"(c[3])
        : "r"(a[0]), "r"(a[1]), "r"(a[2]), "r"(a[3]), "r"(b[0]), "r"(b[1]));
}
// swizzled element fetch: tile is [rows][16 floats], 16B-granule XOR swizzle
__device__ __forceinline__ uint32_t lde(const uint32_t* t, int row, int k) {
    int g = k >> 2;
    return t[row * 16 + (((g ^ ((row >> 1) & 3)) << 2) | (k & 3))];
}

// ===========================================================================
// 3xTF32 GEMM (NT) with pre-split operands:
// C[m,n] = alpha*sum_k A[m,k]*B[n,k], A = Ah+Al, B = Bh+Bl (tf32-exact parts)
// BM=BN=128, BK=16 floats, 3-stage cp.async pipeline (4 tiles/stage),
// 256 threads, warp grid 2m x 4n, warp tile 64x32, m16n8k8 tf32.
// Epilogue MODEs:
//  0: O1 = alpha*acc (+bias1)
//  1: v = relu(acc)^2; split -> O1(hi), O2(lo)
//  2: QK: col<64 -> Q=acc+bias1[col] split->(O1,O2); else K=acc+bias2 ->(O3,O4)
//  3: v = acc+bias1; r = sigmoid(ex1)* (v+ex2); split -> O1, O2
//  4: O1 = ex1 + acc
//  5: O1 = ex1 + sigmoid(ex2)*acc
// Requires M%128==0, N%128==0, K%16==0, K>=64.
// ===========================================================================
#define BM   128
#define BN   128
#define BKF  16
#define TILE_BYTES (BM * BKF * 4)        // 8192
#define STG_BYTES  (4 * TILE_BYTES)      // 32768 (Ah, Al, Bh, Bl)
#define NSTG 3
#define GEMM_DSMEM (NSTG * STG_BYTES)    // 98304

__device__ __forceinline__ void load_stage4(
    uint32_t sbase, int stage,
    const float* __restrict__ Ah, const float* __restrict__ Al,
    const float* __restrict__ Bh, const float* __restrict__ Bl,
    int bm, int bn, int k0, int K, int tid)
{
    uint32_t s = sbase + stage * STG_BYTES;
    int row = tid >> 1;            // 0..127
    int g0 = (tid & 1) * 2;        // granule pair
#pragma unroll
    for (int j = 0; j < 2; j++) {
        int g = g0 + j;
        uint32_t so = (uint32_t)(row * 64 + ((g ^ ((row >> 1) & 3)) << 4));
        long ao = (long)(bm + row) * K + k0 + g * 4;
        long bo = (long)(bn + row) * K + k0 + g * 4;
        cp16(s + so,                  Ah + ao);
        cp16(s + TILE_BYTES + so,     Al + ao);
        cp16(s + 2 * TILE_BYTES + so, Bh + bo);
        cp16(s + 3 * TILE_BYTES + so, Bl + bo);
    }
}

template<int MODE>
__global__ void __launch_bounds__(256) gemm_mma(
    const float* __restrict__ Ah, const float* __restrict__ Al,
    const float* __restrict__ Bh, const float* __restrict__ Bl,
    const float* __restrict__ bias1, const float* __restrict__ bias2,
    const float* __restrict__ ex1, const float* __restrict__ ex2,
    float* __restrict__ O1, float* __restrict__ O2,
    float* __restrict__ O3, float* __restrict__ O4,
    int M, int N, int K, float alpha, long sA, long sB, long sC)
{
    extern __shared__ __align__(16) char dsm[];

    Ah += (long)blockIdx.z * sA;  Al += (long)blockIdx.z * sA;
    Bh += (long)blockIdx.z * sB;  Bl += (long)blockIdx.z * sB;
    O1 += (long)blockIdx.z * sC;

    const int tid  = threadIdx.x;
    const int wid  = tid >> 5;
    const int lane = tid & 31;
    const int wm   = wid & 1;
    const int wn   = wid >> 1;
    const int bm = blockIdx.y * BM;
    const int bn = blockIdx.x * BN;
    const int KT = K / BKF;

    uint32_t sbase = smem_u32(dsm);

    float acc[4][4][4];
#pragma unroll
    for (int i = 0; i < 4; i++)
#pragma unroll
        for (int j = 0; j < 4; j++)
#pragma unroll
            for (int r = 0; r < 4; r++) acc[i][j][r] = 0.f;

    // prologue: stages 0, 1 (KT >= 4 always)
    load_stage4(sbase, 0, Ah, Al, Bh, Bl, bm, bn, 0, K, tid);
    asm volatile("cp.async.commit_group;" ::: "memory");
    load_stage4(sbase, 1, Ah, Al, Bh, Bl, bm, bn, BKF, K, tid);
    asm volatile("cp.async.commit_group;" ::: "memory");

    const int lr = lane >> 2;   // 0..7
    const int lk = lane & 3;    // 0..3

    int stage = 0;
    for (int kt = 0; kt < KT; kt++) {
        int ps = kt + 2;
        if (ps < KT) {
            int pstage = stage + 2; if (pstage >= NSTG) pstage -= NSTG;
            load_stage4(sbase, pstage, Ah, Al, Bh, Bl, bm, bn, ps * BKF, K, tid);
        }
        asm volatile("cp.async.commit_group;" ::: "memory");
        asm volatile("cp.async.wait_group 2;" ::: "memory");
        __syncthreads();

        const uint32_t* sah = (const uint32_t*)(dsm + (size_t)stage * STG_BYTES);
        const uint32_t* sal = sah + 2048;
        const uint32_t* sbh = sah + 4096;
        const uint32_t* sbl = sah + 6144;

#pragma unroll
        for (int ks = 0; ks < 2; ks++) {
            int kb = ks * 8;
            uint32_t ah[4][4], al[4][4], bh[4][2], bl[4][2];
#pragma unroll
            for (int mf = 0; mf < 4; mf++) {
                int r0 = wm * 64 + mf * 16 + lr;
                ah[mf][0] = lde(sah, r0,     kb + lk);
                ah[mf][1] = lde(sah, r0 + 8, kb + lk);
                ah[mf][2] = lde(sah, r0,     kb + lk + 4);
                ah[mf][3] = lde(sah, r0 + 8, kb + lk + 4);
                al[mf][0] = lde(sal, r0,     kb + lk);
                al[mf][1] = lde(sal, r0 + 8, kb + lk);
                al[mf][2] = lde(sal, r0,     kb + lk + 4);
                al[mf][3] = lde(sal, r0 + 8, kb + lk + 4);
            }
#pragma unroll
            for (int nf = 0; nf < 4; nf++) {
                int n0 = wn * 32 + nf * 8 + lr;
                bh[nf][0] = lde(sbh, n0, kb + lk);
                bh[nf][1] = lde(sbh, n0, kb + lk + 4);
                bl[nf][0] = lde(sbl, n0, kb + lk);
                bl[nf][1] = lde(sbl, n0, kb + lk + 4);
            }
#pragma unroll
            for (int mf = 0; mf < 4; mf++)
#pragma unroll
                for (int nf = 0; nf < 4; nf++) {
                    mma1688(acc[mf][nf], al[mf], bh[nf]);   // lo*hi
                    mma1688(acc[mf][nf], ah[mf], bl[nf]);   // hi*lo
                    mma1688(acc[mf][nf], ah[mf], bh[nf]);   // hi*hi
                }
        }
        __syncthreads();
        stage++; if (stage >= NSTG) stage = 0;
    }

    // epilogue
#pragma unroll
    for (int mf = 0; mf < 4; mf++) {
        int r0 = bm + wm * 64 + mf * 16 + lr;
#pragma unroll
        for (int nf = 0; nf < 4; nf++) {
            int c0 = bn + wn * 32 + nf * 8 + lk * 2;
#pragma unroll
            for (int h = 0; h < 2; h++) {
                int row = r0 + h * 8;
                long idx = (long)row * N + c0;
                float vx = acc[mf][nf][2 * h + 0] * alpha;
                float vy = acc[mf][nf][2 * h + 1] * alpha;
                if (MODE == 0) {
                    if (bias1) { vx += bias1[c0]; vy += bias1[c0 + 1]; }
                    *(float2*)(O1 + idx) = make_float2(vx, vy);
                } else if (MODE == 1) {
                    vx = fmaxf(vx, 0.f); vx *= vx;
                    vy = fmaxf(vy, 0.f); vy *= vy;
                    float hx, lx, hy, ly;
                    fsplit(vx, hx, lx); fsplit(vy, hy, ly);
                    *(float2*)(O1 + idx) = make_float2(hx, hy);
                    *(float2*)(O2 + idx) = make_float2(lx, ly);
                } else if (MODE == 2) {
                    int col = c0;          // 0..127, pair same side
                    float* oh; float* ol; int cc;
                    if (col < 64) {
                        vx += bias1[col]; vy += bias1[col + 1];
                        oh = O1; ol = O2; cc = col;
                    } else {
                        vx += bias2[col - 64]; vy += bias2[col - 63];
                        oh = O3; ol = O4; cc = col - 64;
                    }
                    long qidx = (long)row * 64 + cc;
                    float hx, lx, hy, ly;
                    fsplit(vx, hx, lx); fsplit(vy, hy, ly);
                    *(float2*)(oh + qidx) = make_float2(hx, hy);
                    *(float2*)(ol + qidx) = make_float2(lx, ly);
                } else if (MODE == 3) {
                    vx += bias1[c0]; vy += bias1[c0 + 1];
                    float rx = sigmoidf_(ex1[idx])     * (vx + ex2[idx]);
                    float ry = sigmoidf_(ex1[idx + 1]) * (vy + ex2[idx + 1]);
                    float hx, lx, hy, ly;
                    fsplit(rx, hx, lx); fsplit(ry, hy, ly);
                    *(float2*)(O1 + idx) = make_float2(hx, hy);
                    *(float2*)(O2 + idx) = make_float2(lx, ly);
                } else if (MODE == 4) {
                    *(float2*)(O1 + idx) = make_float2(ex1[idx] + vx, ex1[idx + 1] + vy);
                } else { // MODE 5
                    float rx = ex1[idx]     + sigmoidf_(ex2[idx])     * vx;
                    float ry = ex1[idx + 1] + sigmoidf_(ex2[idx + 1]) * vy;
                    *(float2*)(O1 + idx) = make_float2(rx, ry);
                }
            }
        }
    }
}

// ---------------------------------------------------------------------------
// Weight / array split: hi/lo tf32 decomposition
// ---------------------------------------------------------------------------
__global__ void __launch_bounds__(256) split_arr(
    const float* __restrict__ src, float* __restrict__ hi, float* __restrict__ lo, long n)
{
    long i = (long)blockIdx.x * blockDim.x + threadIdx.x;
    if (i < n) {
        float h, l;
        fsplit(src[i], h, l);
        hi[i] = h; lo[i] = l;
    }
}

// ---------------------------------------------------------------------------
// RMSNorm -> hi/lo
// ---------------------------------------------------------------------------
__global__ void __launch_bounds__(256) rmsnorm_kernel(
    const float* __restrict__ x, const float* __restrict__ w,
    float* __restrict__ ohi, float* __restrict__ olo)
{
    long row = blockIdx.x;
    const float* xr = x + row * D_DIM;
    int tid = threadIdx.x;

    float s = 0.f;
#pragma unroll
    for (int d = 0; d < 4; d++) {
        float v = xr[tid + d * 256];
        s += v * v;
    }
#pragma unroll
    for (int o = 16; o > 0; o >>= 1) s += __shfl_xor_sync(0xffffffffu, s, o);

    __shared__ float red[8];
    __shared__ float s_inv;
    if ((tid & 31) == 0) red[tid >> 5] = s;
    __syncthreads();
    if (tid == 0) {
        float t = 0.f;
#pragma unroll
        for (int i = 0; i < 8; i++) t += red[i];
        s_inv = 1.0f / (sqrtf(t / (float)D_DIM) + 1e-8f);
    }
    __syncthreads();
    float inv = s_inv;
#pragma unroll
    for (int d = 0; d < 4; d++) {
        int c = tid + d * 256;
        float v = w[c] * xr[c] * inv;
        float h, l; fsplit(v, h, l);
        ohi[row * D_DIM + c] = h;
        olo[row * D_DIM + c] = l;
    }
}

// ---------------------------------------------------------------------------
// Token-shift mixing: h given as hi+lo; outputs hi/lo for both mixes
// ---------------------------------------------------------------------------
__global__ void __launch_bounds__(256) mix2_kernel(
    const float* __restrict__ hh, const float* __restrict__ hl,
    const float* __restrict__ mA, const float* __restrict__ mB,
    float* __restrict__ oAh, float* __restrict__ oAl,
    float* __restrict__ oBh, float* __restrict__ oBl)
{
    long row = blockIdx.x;
    long t = row & (S_LEN - 1);
    long prev = (t == 0) ? row : row - 1;
    int tid = threadIdx.x;
#pragma unroll
    for (int d = 0; d < 4; d++) {
        int c = tid + d * 256;
        long ci = row * D_DIM + c;
        long pi = prev * D_DIM + c;
        float cur = hh[ci] + hl[ci];
        float pv  = hh[pi] + hl[pi];
        float a = mA[c], b = mB[c];
        float va = cur * a + pv * (1.f - a);
        float vb = cur * b + pv * (1.f - b);
        float h, l;
        fsplit(va, h, l); oAh[ci] = h; oAl[ci] = l;
        fsplit(vb, h, l); oBh[ci] = h; oBl[ci] = l;
    }
}

// ---------------------------------------------------------------------------
// Sparse attention: top-32, softmax, attn@V -> hi/lo. One block per query.
// ---------------------------------------------------------------------------
__global__ void __launch_bounds__(256) sparse_attn_kernel(
    const float* __restrict__ scores, const float* __restrict__ V,
    float* __restrict__ ohi, float* __restrict__ olo)
{
    __shared__ float sc[S_LEN];
    __shared__ float selV[TOPK];
    __shared__ int   selI[TOPK];
    __shared__ float rv[8];
    __shared__ int   ri[8];
    __shared__ float wsel[TOPK];

    long row = blockIdx.x;
    long b = row >> 12;
    int tid = threadIdx.x;

    const float* srow = scores + row * S_LEN;
    for (int i = tid; i < S_LEN; i += 256) sc[i] = srow[i];
    __syncthreads();

    for (int it = 0; it < TOPK; it++) {
        float bv = NEG_INF;
        int bi = 0x7fffffff;
        for (int i = tid; i < S_LEN; i += 256) {
            float v = sc[i];
            if (v > bv || (v == bv && i < bi)) { bv = v; bi = i; }
        }
#pragma unroll
        for (int o = 16; o > 0; o >>= 1) {
            float ov = __shfl_down_sync(0xffffffffu, bv, o);
            int   oi = __shfl_down_sync(0xffffffffu, bi, o);
            if (ov > bv || (ov == bv && oi < bi)) { bv = ov; bi = oi; }
        }
        if ((tid & 31) == 0) { rv[tid >> 5] = bv; ri[tid >> 5] = bi; }
        __syncthreads();
        if (tid == 0) {
            float fv = rv[0]; int fi = ri[0];
#pragma unroll
            for (int w = 1; w < 8; w++) {
                if (rv[w] > fv || (rv[w] == fv && ri[w] < fi)) { fv = rv[w]; fi = ri[w]; }
            }
            selV[it] = fv; selI[it] = fi;
            sc[fi] = NEG_INF;
        }
        __syncthreads();
    }

    if (tid < TOPK) {
        float m = selV[0];
        float e = expf(selV[tid] - m);
        float s = e;
#pragma unroll
        for (int o = 16; o > 0; o >>= 1) s += __shfl_xor_sync(0xffffffffu, s, o);
        wsel[tid] = e / s;
    }
    __syncthreads();

    float acc[4] = {0.f, 0.f, 0.f, 0.f};
    const float* Vb = V + b * (long)S_LEN * D_DIM;
#pragma unroll 1
    for (int j = 0; j < TOPK; j++) {
        float w = wsel[j];
        const float* vr = Vb + (long)selI[j] * D_DIM;
#pragma unroll
        for (int d = 0; d < 4; d++) acc[d] += w * vr[tid + d * 256];
    }
#pragma unroll
    for (int d = 0; d < 4; d++) {
        float h, l; fsplit(acc[d], h, l);
        ohi[row * D_DIM + tid + d * 256] = h;
        olo[row * D_DIM + tid + d * 256] = l;
    }
}

// ---------------------------------------------------------------------------
// Host launchers
// ---------------------------------------------------------------------------
static void launch_g(int mode,
    const float* Ah, const float* Al, const float* Bh, const float* Bl,
    const float* b1, const float* b2, const float* e1, const float* e2,
    float* O1, float* O2, float* O3, float* O4,
    int M, int N, int K, float alpha, int batch, long sA, long sB, long sC)
{
    dim3 grid(N / BN, M / BM, batch);
    switch (mode) {
    case 0: gemm_mma<0><<<grid, 256, GEMM_DSMEM>>>(Ah,Al,Bh,Bl,b1,b2,e1,e2,O1,O2,O3,O4,M,N,K,alpha,sA,sB,sC); break;
    case 1: gemm_mma<1><<<grid, 256, GEMM_DSMEM>>>(Ah,Al,Bh,Bl,b1,b2,e1,e2,O1,O2,O3,O4,M,N,K,alpha,sA,sB,sC); break;
    case 2: gemm_mma<2><<<grid, 256, GEMM_DSMEM>>>(Ah,Al,Bh,Bl,b1,b2,e1,e2,O1,O2,O3,O4,M,N,K,alpha,sA,sB,sC); break;
    case 3: gemm_mma<3><<<grid, 256, GEMM_DSMEM>>>(Ah,Al,Bh,Bl,b1,b2,e1,e2,O1,O2,O3,O4,M,N,K,alpha,sA,sB,sC); break;
    case 4: gemm_mma<4><<<grid, 256, GEMM_DSMEM>>>(Ah,Al,Bh,Bl,b1,b2,e1,e2,O1,O2,O3,O4,M,N,K,alpha,sA,sB,sC); break;
    default: gemm_mma<5><<<grid, 256, GEMM_DSMEM>>>(Ah,Al,Bh,Bl,b1,b2,e1,e2,O1,O2,O3,O4,M,N,K,alpha,sA,sB,sC); break;
    }
}

static void launch_split(const float* src, float* hi, float* lo, long n) {
    split_arr<<<(int)((n + 255) / 256), 256>>>(src, hi, lo, n);
}

extern "C" void kernel_launch(void* const* d_in, const int* in_sizes, int n_in,
                              void* d_out, int out_size)
{
    const float* x         = (const float*)d_in[0];
    const float* norm1_w   = (const float*)d_in[1];
    const float* tm_mix_v  = (const float*)d_in[3];
    const float* tm_mix_r  = (const float*)d_in[4];
    const float* tm_value_w  = (const float*)d_in[6];
    const float* tm_recept_w = (const float*)d_in[7];
    const float* tm_out_w    = (const float*)d_in[8];
    const float* sa_q_w    = (const float*)d_in[9];
    const float* sa_q_b    = (const float*)d_in[10];
    const float* sa_k_w    = (const float*)d_in[11];
    const float* sa_k_b    = (const float*)d_in[12];
    const float* sa_v_w    = (const float*)d_in[13];
    const float* sa_v_b    = (const float*)d_in[14];
    const float* sa_o_w    = (const float*)d_in[15];
    const float* sa_o_b    = (const float*)d_in[16];
    const float* norm2_w   = (const float*)d_in[17];
    const float* cm_mix_k  = (const float*)d_in[18];
    const float* cm_mix_r  = (const float*)d_in[19];
    const float* cm_key_w    = (const float*)d_in[20];
    const float* cm_recept_w = (const float*)d_in[21];
    const float* cm_value_w  = (const float*)d_in[22];
    float* out = (float*)d_out;

    cudaFuncSetAttribute(gemm_mma<0>, cudaFuncAttributeMaxDynamicSharedMemorySize, GEMM_DSMEM);
    cudaFuncSetAttribute(gemm_mma<1>, cudaFuncAttributeMaxDynamicSharedMemorySize, GEMM_DSMEM);
    cudaFuncSetAttribute(gemm_mma<2>, cudaFuncAttributeMaxDynamicSharedMemorySize, GEMM_DSMEM);
    cudaFuncSetAttribute(gemm_mma<3>, cudaFuncAttributeMaxDynamicSharedMemorySize, GEMM_DSMEM);
    cudaFuncSetAttribute(gemm_mma<4>, cudaFuncAttributeMaxDynamicSharedMemorySize, GEMM_DSMEM);
    cudaFuncSetAttribute(gemm_mma<5>, cudaFuncAttributeMaxDynamicSharedMemorySize, GEMM_DSMEM);

    float* sp = nullptr;
    cudaGetSymbolAddress((void**)&sp, g_scratch);

    float* hH   = sp + O_HHI;   float* hL   = sp + O_HLO;
    float* xvH  = sp + O_XVHI;  float* xvL  = sp + O_XVLO;
    float* xrH  = sp + O_XRHI;  float* xrL  = sp + O_XRLO;
    float* Vtm  = sp + O_VTM;
    float* Rtm  = sp + O_RTM;
    float* Vv   = sp + O_VV;       // later rkv_lo
    float* atH  = sp + O_ATTNHI;  float* atL = sp + O_ATTNLO;
    float* rkH  = sp + O_RKVHI;   float* rkL = Vv;
    float* x2   = sp + O_X2;
    float* R2   = sp + O_R2;
    float* QH   = sp + O_QHI;  float* QL = sp + O_QLO;
    float* KH   = sp + O_KHI;  float* KL = sp + O_KLO;
    float* SCo  = sp + O_SC;
    float* KcH  = sp + O_KCHI; float* KcL = sp + O_KCLO;

    float* wTMVh = sp + O_WTMV; float* wTMVl = wTMVh + WDD;
    float* wTMRh = sp + O_WTMR; float* wTMRl = wTMRh + WDD;
    float* wSAVh = sp + O_WSAV; float* wSAVl = wSAVh + WDD;
    float* wSAOh = sp + O_WSAO; float* wSAOl = wSAOh + WDD;
    float* wTMOh = sp + O_WTMO; float* wTMOl = wTMOh + WDD;
    float* wCMRh = sp + O_WCMR; float* wCMRl = wCMRh + WDD;
    float* wCMKh = sp + O_WCMK; float* wCMKl = wCMKh + 4194304L;
    float* wCMVh = sp + O_WCMV; float* wCMVl = wCMVh + 4194304L;
    float* wQKh  = sp + O_WQK;  float* wQKl  = wQKh + 131072L;

    // --- weight splits (per launch; deterministic) ---
    launch_split(tm_value_w,  wTMVh, wTMVl, WDD);
    launch_split(tm_recept_w, wTMRh, wTMRl, WDD);
    launch_split(sa_v_w,      wSAVh, wSAVl, WDD);
    launch_split(sa_o_w,      wSAOh, wSAOl, WDD);
    launch_split(tm_out_w,    wTMOh, wTMOl, WDD);
    launch_split(cm_recept_w, wCMRh, wCMRl, WDD);
    launch_split(cm_key_w,    wCMKh, wCMKl, 4194304L);
    launch_split(cm_value_w,  wCMVh, wCMVl, 4194304L);
    launch_split(sa_q_w, wQKh,          wQKl,          65536L);   // rows 0..63
    launch_split(sa_k_w, wQKh + 65536L, wQKl + 65536L, 65536L);   // rows 64..127

    // --- time-mix branch ---
    rmsnorm_kernel<<<NROWS, 256>>>(x, norm1_w, hH, hL);
    mix2_kernel<<<NROWS, 256>>>(hH, hL, tm_mix_v, tm_mix_r, xvH, xvL, xrH, xrL);

    launch_g(0, xvH, xvL, wTMVh, wTMVl, nullptr, nullptr, nullptr, nullptr,
             Vtm, nullptr, nullptr, nullptr, NROWS, D_DIM, D_DIM, 1.f, 1, 0, 0, 0);
    launch_g(0, xrH, xrL, wTMRh, wTMRl, nullptr, nullptr, nullptr, nullptr,
             Rtm, nullptr, nullptr, nullptr, NROWS, D_DIM, D_DIM, 1.f, 1, 0, 0, 0);

    // Q||K projection (N=128), split outputs + biases
    launch_g(2, hH, hL, wQKh, wQKl, sa_q_b, sa_k_b, nullptr, nullptr,
             QH, QL, KH, KL, NROWS, 128, D_DIM, 1.f, 1, 0, 0, 0);

    launch_g(0, hH, hL, wSAVh, wSAVl, sa_v_b, nullptr, nullptr, nullptr,
             Vv, nullptr, nullptr, nullptr, NROWS, D_DIM, D_DIM, 1.f, 1, 0, 0, 0);

    // scores[b] = (Q[b] @ K[b]^T) / 8   (batched over B)
    launch_g(0, QH, QL, KH, KL, nullptr, nullptr, nullptr, nullptr,
             SCo, nullptr, nullptr, nullptr, S_LEN, S_LEN, A_DIM, 0.125f, B_SZ,
             (long)S_LEN * A_DIM, (long)S_LEN * A_DIM, (long)S_LEN * S_LEN);

    sparse_attn_kernel<<<NROWS, 256>>>(SCo, Vv, atH, atL);

    // sa_o + gate fusion: rkv = sigmoid(Rtm) * (attn@W_o + b_o + Vtm), split out
    launch_g(3, atH, atL, wSAOh, wSAOl, sa_o_b, nullptr, Rtm, Vtm,
             rkH, rkL, nullptr, nullptr, NROWS, D_DIM, D_DIM, 1.f, 1, 0, 0, 0);

    // tm_out + residual: x2 = x + rkv @ W_out
    launch_g(4, rkH, rkL, wTMOh, wTMOl, nullptr, nullptr, x, nullptr,
             x2, nullptr, nullptr, nullptr, NROWS, D_DIM, D_DIM, 1.f, 1, 0, 0, 0);

    // --- channel-mix branch ---
    rmsnorm_kernel<<<NROWS, 256>>>(x2, norm2_w, hH, hL);
    mix2_kernel<<<NROWS, 256>>>(hH, hL, cm_mix_k, cm_mix_r, xvH, xvL, xrH, xrL);

    // Kc = relu(xk2 @ W_k)^2, split out
    launch_g(1, xvH, xvL, wCMKh, wCMKl, nullptr, nullptr, nullptr, nullptr,
             KcH, KcL, nullptr, nullptr, NROWS, DI_DIM, D_DIM, 1.f, 1, 0, 0, 0);
    launch_g(0, xrH, xrL, wCMRh, wCMRl, nullptr, nullptr, nullptr, nullptr,
             R2, nullptr, nullptr, nullptr, NROWS, D_DIM, D_DIM, 1.f, 1, 0, 0, 0);

    // out = x2 + sigmoid(R2) * (Kc @ W_v)
    launch_g(5, KcH, KcL, wCMVh, wCMVl, nullptr, nullptr, x2, R2,
             out, nullptr, nullptr, nullptr, NROWS, D_DIM, DI_DIM, 1.f, 1, 0, 0, 0);
}

// round 9
// speedup vs baseline: 1.8599x; 1.8599x over previous
#include <cuda_runtime.h>
#include <cuda_bf16.h>
#include <math.h>
#include <stdint.h>

// Problem constants
#define D_DIM   1024
#define S_LEN   4096
#define B_SZ    2
#define A_DIM   64
#define DI_DIM  4096
#define TOPK    32
#define NROWS   (B_SZ * S_LEN)                 // 8192
#define ROWELEMS ((long)NROWS * D_DIM)         // 8,388,608

#define NEG_INF (-3.402823466e38f)

// ---------------------------------------------------------------------------
// Scratch layout (float offsets; bf16 arrays overlay pairs of floats)
// ---------------------------------------------------------------------------
static const long O_HF   = 0L;
static const long O_VTM  = 8388608L;
static const long O_RTM  = 16777216L;
static const long O_VV   = 25165824L;
static const long O_X2   = 33554432L;
static const long O_R2   = 41943040L;
static const long O_Q    = 50331648L;   // 524288 fp32
static const long O_K    = 50855936L;   // 524288 fp32
static const long O_WQKF = 51380224L;   // 131072 fp32 (concat q/k weights)
static const long O_SC   = 51511296L;   // 33554432 fp32
// bf16 arrays (float-offset; each float slot holds 2 bf16)
static const long O_BHB = 85065728L;    // h hi      (8.4M bf16 = 4194304 floats)
static const long O_BHL = 89260032L;
static const long O_XVH = 93454336L;
static const long O_XVL = 97648640L;
static const long O_XRH = 101842944L;
static const long O_XRL = 106037248L;
static const long O_ATH = 110231552L;
static const long O_ATL = 114425856L;
static const long O_RKH = 118620160L;
static const long O_RKL = 122814464L;
static const long O_KCH = 127008768L;   // 33.5M bf16 = 16777216 floats
static const long O_KCL = 143785984L;
static const long O_WB  = 160563200L;   // weight splits (bf16)
// D*D weight pairs: hi 524288 + lo 524288 floats each pair
static const long O_WTMV = O_WB;
static const long O_WTMR = O_WTMV + 1048576L;
static const long O_WSAV = O_WTMR + 1048576L;
static const long O_WSAO = O_WSAV + 1048576L;
static const long O_WTMO = O_WSAO + 1048576L;
static const long O_WCMR = O_WTMO + 1048576L;
static const long O_WCMK = O_WCMR + 1048576L;   // 4.2M bf16 hi + lo = 4194304 floats
static const long O_WCMV = O_WCMK + 4194304L;
// end = O_WCMV + 4194304 = 175243264

__device__ __align__(16) float g_scratch[175243264];

// ===========================================================================
// helpers
// ===========================================================================
__device__ __forceinline__ uint32_t smem_u32(const void* p) {
    uint32_t a;
    asm("{ .reg .u64 t; cvta.to.shared.u64 t, %1; cvt.u32.u64 %0, t; }"
        : "=r"(a) : "l"(p));
    return a;
}
__device__ __forceinline__ uint32_t f2tf32(float x) {
    uint32_t r;
    asm("cvt.rna.tf32.f32 %0, %1;" : "=r"(r) : "f"(x));
    return r;
}
__device__ __forceinline__ void split_tf32(uint32_t xbits, uint32_t& hi, uint32_t& lo) {
    float x = __uint_as_float(xbits);
    hi = f2tf32(x);
    lo = f2tf32(x - __uint_as_float(hi));
}
__device__ __forceinline__ float sigmoidf_(float x) { return 1.f / (1.f + expf(-x)); }

__device__ __forceinline__ void cp16(uint32_t s, const void* g) {
    asm volatile("cp.async.cg.shared.global [%0], [%1], 16;" :: "r"(s), "l"(g));
}

// scalar bf16 hi/lo split store
__device__ __forceinline__ void bsplit_store(__nv_bfloat16* H, __nv_bfloat16* L,
                                             long i, float v) {
    __nv_bfloat16 h = __float2bfloat16(v);
    H[i] = h;
    L[i] = __float2bfloat16(v - __bfloat162float(h));
}
// paired (2-elem) bf16 hi/lo split store at even index
__device__ __forceinline__ void bpair_store(__nv_bfloat16* H, __nv_bfloat16* L,
                                            long idx, float vx, float vy) {
    __nv_bfloat16 hx = __float2bfloat16(vx);
    __nv_bfloat16 hy = __float2bfloat16(vy);
    __nv_bfloat16 lx = __float2bfloat16(vx - __bfloat162float(hx));
    __nv_bfloat16 ly = __float2bfloat16(vy - __bfloat162float(hy));
    __nv_bfloat162 hp; hp.x = hx; hp.y = hy;
    __nv_bfloat162 lp; lp.x = lx; lp.y = ly;
    *(__nv_bfloat162*)(H + idx) = hp;
    *(__nv_bfloat162*)(L + idx) = lp;
}

__device__ __forceinline__ void mma1688(float* c, const uint32_t* a, const uint32_t* b) {
    asm volatile(
        "mma.sync.aligned.m16n8k8.row.col.f32.tf32.tf32.f32 "
        "{%0,%1,%2,%3}, {%4,%5,%6,%7}, {%8,%9}, {%0,%1,%2,%3};"
        : "+f"(c[0]), "+f"(c[1]), "+f"(c[2]), "+f"(c[3])
        : "r"(a[0]), "r"(a[1]), "r"(a[2]), "r"(a[3]), "r"(b[0]), "r"(b[1]));
}
__device__ __forceinline__ void mma16816(float* c, const uint32_t* a, const uint32_t* b) {
    asm volatile(
        "mma.sync.aligned.m16n8k16.row.col.f32.bf16.bf16.f32 "
        "{%0,%1,%2,%3}, {%4,%5,%6,%7}, {%8,%9}, {%0,%1,%2,%3};"
        : "+f"(c[0]), "+f"(c[1]), "+f"(c[2]), "+f"(c[3])
        : "r"(a[0]), "r"(a[1]), "r"(a[2]), "r"(a[3]), "r"(b[0]), "r"(b[1]));
}

// ===========================================================================
// bf16x3 GEMM (NT): C = (Ah+Al)(Bh+Bl)^T via al*bh + ah*bl + ah*bh
// BM=BN=128, BK=32 bf16, 3-stage cp.async, 256 thr, warp 2m x 4n, 64x32 tile.
// Tiles [128 rows][64B], 16B-granule XOR swizzle g^=((row>>1)&3).
// MODEs: 0: Of = acc (+bias1)     1: relu(acc)^2 -> (Oh,Ol)
//        3: sigmoid(ex1)*(acc+bias1+ex2) -> (Oh,Ol)
//        4: Of = ex1 + acc        5: Of = ex1 + sigmoid(ex2)*acc
// Requires M%128==0, N%128==0, K%32==0.
// ===========================================================================
#define BTILE 8192                    // 128*32*2
#define BSTG  (4 * BTILE)             // 32768
#define BNSTG 3
#define BF_DSMEM (BNSTG * BSTG)       // 98304

__device__ __forceinline__ void load_stage_bf(
    uint32_t sbase, int stage,
    const __nv_bfloat16* __restrict__ Ah, const __nv_bfloat16* __restrict__ Al,
    const __nv_bfloat16* __restrict__ Bh, const __nv_bfloat16* __restrict__ Bl,
    int bm, int bn, int k0, int K, int tid)
{
    uint32_t s = sbase + stage * BSTG;
#pragma unroll
    for (int j = 0; j < 2; j++) {
        int gi = tid + j * 256;        // 0..511
        int row = gi >> 2, g = gi & 3;
        uint32_t so = (uint32_t)(row * 64 + ((g ^ ((row >> 1) & 3)) << 4));
        long ao = (long)(bm + row) * K + k0 + g * 8;
        long bo = (long)(bn + row) * K + k0 + g * 8;
        cp16(s + so,             Ah + ao);
        cp16(s + BTILE + so,     Al + ao);
        cp16(s + 2 * BTILE + so, Bh + bo);
        cp16(s + 3 * BTILE + so, Bl + bo);
    }
}

template<int MODE>
__global__ void __launch_bounds__(256) gemm_bf(
    const __nv_bfloat16* __restrict__ Ah, const __nv_bfloat16* __restrict__ Al,
    const __nv_bfloat16* __restrict__ Bh, const __nv_bfloat16* __restrict__ Bl,
    const float* __restrict__ bias1,
    const float* __restrict__ ex1, const float* __restrict__ ex2,
    float* __restrict__ Of,
    __nv_bfloat16* __restrict__ Oh, __nv_bfloat16* __restrict__ Ol,
    int M, int N, int K)
{
    extern __shared__ __align__(16) char dsm[];

    const int tid  = threadIdx.x;
    const int wid  = tid >> 5;
    const int lane = tid & 31;
    const int wm   = wid & 1;
    const int wn   = wid >> 1;
    const int bm = blockIdx.y * 128;
    const int bn = blockIdx.x * 128;
    const int KT = K / 32;
    const int lr = lane >> 2, lk = lane & 3;

    float acc[4][4][4];
#pragma unroll
    for (int i = 0; i < 4; i++)
#pragma unroll
        for (int j = 0; j < 4; j++)
#pragma unroll
            for (int r = 0; r < 4; r++) acc[i][j][r] = 0.f;

    // per-thread swizzled base offsets (bits 4-5 hold xr; g XORs there)
    uint32_t PA[4][2], PB[4];
#pragma unroll
    for (int mf = 0; mf < 4; mf++)
#pragma unroll
        for (int i = 0; i < 2; i++) {
            int row = wm * 64 + mf * 16 + lr + i * 8;
            PA[mf][i] = (uint32_t)(row * 64 + lk * 4 + (((row >> 1) & 3) << 4));
        }
#pragma unroll
    for (int nf = 0; nf < 4; nf++) {
        int row = wn * 32 + nf * 8 + lr;
        PB[nf] = (uint32_t)(row * 64 + lk * 4 + (((row >> 1) & 3) << 4));
    }

    uint32_t sbase = smem_u32(dsm);
    load_stage_bf(sbase, 0, Ah, Al, Bh, Bl, bm, bn, 0, K, tid);
    asm volatile("cp.async.commit_group;" ::: "memory");
    load_stage_bf(sbase, 1, Ah, Al, Bh, Bl, bm, bn, 32, K, tid);
    asm volatile("cp.async.commit_group;" ::: "memory");

    int stage = 0;
    for (int kt = 0; kt < KT; kt++) {
        int ps = kt + 2;
        if (ps < KT) {
            int pstage = stage + 2; if (pstage >= BNSTG) pstage -= BNSTG;
            load_stage_bf(sbase, pstage, Ah, Al, Bh, Bl, bm, bn, ps * 32, K, tid);
        }
        asm volatile("cp.async.commit_group;" ::: "memory");
        asm volatile("cp.async.wait_group 2;" ::: "memory");
        __syncthreads();

        const char* t0  = dsm + (size_t)stage * BSTG;
        const char* tAh = t0;
        const char* tAl = t0 + BTILE;
        const char* tBh = t0 + 2 * BTILE;
        const char* tBl = t0 + 3 * BTILE;

#pragma unroll
        for (int ks = 0; ks < 2; ks++) {
            uint32_t g0 = (uint32_t)((ks * 2) << 4);
            uint32_t g1 = (uint32_t)((ks * 2 + 1) << 4);
            uint32_t ah[4][4], al[4][4], bh[4][2], bl[4][2];
#pragma unroll
            for (int mf = 0; mf < 4; mf++) {
                ah[mf][0] = *(const uint32_t*)(tAh + (PA[mf][0] ^ g0));
                ah[mf][1] = *(const uint32_t*)(tAh + (PA[mf][1] ^ g0));
                ah[mf][2] = *(const uint32_t*)(tAh + (PA[mf][0] ^ g1));
                ah[mf][3] = *(const uint32_t*)(tAh + (PA[mf][1] ^ g1));
                al[mf][0] = *(const uint32_t*)(tAl + (PA[mf][0] ^ g0));
                al[mf][1] = *(const uint32_t*)(tAl + (PA[mf][1] ^ g0));
                al[mf][2] = *(const uint32_t*)(tAl + (PA[mf][0] ^ g1));
                al[mf][3] = *(const uint32_t*)(tAl + (PA[mf][1] ^ g1));
            }
#pragma unroll
            for (int nf = 0; nf < 4; nf++) {
                bh[nf][0] = *(const uint32_t*)(tBh + (PB[nf] ^ g0));
                bh[nf][1] = *(const uint32_t*)(tBh + (PB[nf] ^ g1));
                bl[nf][0] = *(const uint32_t*)(tBl + (PB[nf] ^ g0));
                bl[nf][1] = *(const uint32_t*)(tBl + (PB[nf] ^ g1));
            }
#pragma unroll
            for (int mf = 0; mf < 4; mf++)
#pragma unroll
                for (int nf = 0; nf < 4; nf++) {
                    mma16816(acc[mf][nf], al[mf], bh[nf]);
                    mma16816(acc[mf][nf], ah[mf], bl[nf]);
                    mma16816(acc[mf][nf], ah[mf], bh[nf]);
                }
        }
        __syncthreads();
        stage++; if (stage >= BNSTG) stage = 0;
    }

    // epilogue
#pragma unroll
    for (int mf = 0; mf < 4; mf++) {
        int r0 = bm + wm * 64 + mf * 16 + lr;
#pragma unroll
        for (int nf = 0; nf < 4; nf++) {
            int c0 = bn + wn * 32 + nf * 8 + lk * 2;
#pragma unroll
            for (int h = 0; h < 2; h++) {
                int row = r0 + h * 8;
                long idx = (long)row * N + c0;
                float vx = acc[mf][nf][2 * h + 0];
                float vy = acc[mf][nf][2 * h + 1];
                if (MODE == 0) {
                    if (bias1) { vx += bias1[c0]; vy += bias1[c0 + 1]; }
                    *(float2*)(Of + idx) = make_float2(vx, vy);
                } else if (MODE == 1) {
                    vx = fmaxf(vx, 0.f); vx *= vx;
                    vy = fmaxf(vy, 0.f); vy *= vy;
                    bpair_store(Oh, Ol, idx, vx, vy);
                } else if (MODE == 3) {
                    vx += bias1[c0]; vy += bias1[c0 + 1];
                    float rx = sigmoidf_(ex1[idx])     * (vx + ex2[idx]);
                    float ry = sigmoidf_(ex1[idx + 1]) * (vy + ex2[idx + 1]);
                    bpair_store(Oh, Ol, idx, rx, ry);
                } else if (MODE == 4) {
                    *(float2*)(Of + idx) = make_float2(ex1[idx] + vx, ex1[idx + 1] + vy);
                } else { // 5
                    float rx = ex1[idx]     + sigmoidf_(ex2[idx])     * vx;
                    float ry = ex1[idx + 1] + sigmoidf_(ex2[idx + 1]) * vy;
                    *(float2*)(Of + idx) = make_float2(rx, ry);
                }
            }
        }
    }
}

// ===========================================================================
// tf32x3 GEMM (NT) with in-kernel split (fp32 inputs) — precision path.
// MODEs: 0: O1 = alpha*acc (batched via blockIdx.z strides)
//        2: QK: col<64 -> Qf=acc+qb, col>=64 -> Kf=acc+kb (fp32 [row][64])
// ===========================================================================
#define TBKF 16
#define T_A_BYTES (128 * TBKF * 4)      // 8192
#define T_STG     (2 * T_A_BYTES)       // 16384
#define TNSTG 4
#define TF_DSMEM (TNSTG * T_STG)        // 65536

__device__ __forceinline__ uint32_t lde(const uint32_t* t, int row, int k) {
    int g = k >> 2;
    return t[row * 16 + (((g ^ ((row >> 1) & 3)) << 2) | (k & 3))];
}

__device__ __forceinline__ void load_stage_tf(
    uint32_t sbase, int stage, const float* __restrict__ A,
    const float* __restrict__ B, int bm, int bn, int k0, int K, int tid)
{
    uint32_t sa = sbase + stage * T_STG;
    uint32_t sb = sa + T_A_BYTES;
    int row = tid >> 1;
    int g0 = (tid & 1) * 2;
#pragma unroll
    for (int j = 0; j < 2; j++) {
        int g = g0 + j;
        uint32_t so = (uint32_t)(row * 64 + ((g ^ ((row >> 1) & 3)) << 4));
        cp16(sa + so, A + (long)(bm + row) * K + k0 + g * 4);
        cp16(sb + so, B + (long)(bn + row) * K + k0 + g * 4);
    }
}

template<int MODE>
__global__ void __launch_bounds__(256) gemm_tf(
    const float* __restrict__ A, const float* __restrict__ B,
    const float* __restrict__ qb, const float* __restrict__ kb,
    float* __restrict__ O1, float* __restrict__ Qf, float* __restrict__ Kf,
    int M, int N, int K, float alpha, long sA, long sB, long sC)
{
    extern __shared__ __align__(16) char dsm[];

    A += (long)blockIdx.z * sA;
    B += (long)blockIdx.z * sB;
    O1 += (long)blockIdx.z * sC;

    const int tid  = threadIdx.x;
    const int wid  = tid >> 5;
    const int lane = tid & 31;
    const int wm   = wid & 1;
    const int wn   = wid >> 1;
    const int bm = blockIdx.y * 128;
    const int bn = blockIdx.x * 128;
    const int KT = K / TBKF;

    uint32_t sbase = smem_u32(dsm);

    float acc[4][4][4];
#pragma unroll
    for (int i = 0; i < 4; i++)
#pragma unroll
        for (int j = 0; j < 4; j++)
#pragma unroll
            for (int r = 0; r < 4; r++) acc[i][j][r] = 0.f;

#pragma unroll
    for (int s = 0; s < TNSTG - 1; s++) {
        if (s < KT) load_stage_tf(sbase, s, A, B, bm, bn, s * TBKF, K, tid);
        asm volatile("cp.async.commit_group;" ::: "memory");
    }

    const int lr = lane >> 2;
    const int lk = lane & 3;

    for (int kt = 0; kt < KT; kt++) {
        __syncthreads();
        if (kt + 3 < KT)
            load_stage_tf(sbase, (kt + 3) & 3, A, B, bm, bn, (kt + 3) * TBKF, K, tid);
        asm volatile("cp.async.commit_group;" ::: "memory");
        asm volatile("cp.async.wait_group 3;" ::: "memory");
        __syncthreads();

        const uint32_t* sa = (const uint32_t*)(dsm + (size_t)(kt & 3) * T_STG);
        const uint32_t* sb = sa + 128 * TBKF;

#pragma unroll
        for (int ks = 0; ks < 2; ks++) {
            int kbase = ks * 8;
            uint32_t ah[4][4], al[4][4], bh[4][2], bl[4][2];
#pragma unroll
            for (int mf = 0; mf < 4; mf++) {
                int r0 = wm * 64 + mf * 16 + lr;
                split_tf32(lde(sa, r0,     kbase + lk),     ah[mf][0], al[mf][0]);
                split_tf32(lde(sa, r0 + 8, kbase + lk),     ah[mf][1], al[mf][1]);
                split_tf32(lde(sa, r0,     kbase + lk + 4), ah[mf][2], al[mf][2]);
                split_tf32(lde(sa, r0 + 8, kbase + lk + 4), ah[mf][3], al[mf][3]);
            }
#pragma unroll
            for (int nf = 0; nf < 4; nf++) {
                int n0 = wn * 32 + nf * 8 + lr;
                split_tf32(lde(sb, n0, kbase + lk),     bh[nf][0], bl[nf][0]);
                split_tf32(lde(sb, n0, kbase + lk + 4), bh[nf][1], bl[nf][1]);
            }
#pragma unroll
            for (int mf = 0; mf < 4; mf++)
#pragma unroll
                for (int nf = 0; nf < 4; nf++) {
                    mma1688(acc[mf][nf], al[mf], bh[nf]);
                    mma1688(acc[mf][nf], ah[mf], bl[nf]);
                    mma1688(acc[mf][nf], ah[mf], bh[nf]);
                }
        }
    }

#pragma unroll
    for (int mf = 0; mf < 4; mf++) {
        int r0 = bm + wm * 64 + mf * 16 + lr;
#pragma unroll
        for (int nf = 0; nf < 4; nf++) {
            int c0 = bn + wn * 32 + nf * 8 + lk * 2;
#pragma unroll
            for (int h = 0; h < 2; h++) {
                int row = r0 + h * 8;
                float vx = acc[mf][nf][2 * h + 0] * alpha;
                float vy = acc[mf][nf][2 * h + 1] * alpha;
                if (MODE == 0) {
                    *(float2*)(O1 + (long)row * N + c0) = make_float2(vx, vy);
                } else { // MODE 2: Q||K
                    if (c0 < 64) {
                        vx += qb[c0]; vy += qb[c0 + 1];
                        *(float2*)(Qf + (long)row * 64 + c0) = make_float2(vx, vy);
                    } else {
                        vx += kb[c0 - 64]; vy += kb[c0 - 63];
                        *(float2*)(Kf + (long)row * 64 + c0 - 64) = make_float2(vx, vy);
                    }
                }
            }
        }
    }
}

// ---------------------------------------------------------------------------
// Weight split: fp32 -> bf16 hi/lo
// ---------------------------------------------------------------------------
__global__ void __launch_bounds__(256) split_bf(
    const float* __restrict__ src, __nv_bfloat16* __restrict__ h,
    __nv_bfloat16* __restrict__ l, long n)
{
    long i = ((long)blockIdx.x * 256 + threadIdx.x) * 2;
    if (i < n) bpair_store(h, l, i, src[i], src[i + 1]);
}

__global__ void __launch_bounds__(256) concat_qk(
    const float* __restrict__ q, const float* __restrict__ k, float* __restrict__ o)
{
    int i = blockIdx.x * 256 + threadIdx.x;   // n = 131072
    o[i] = (i < 65536) ? q[i] : k[i - 65536];
}

// ---------------------------------------------------------------------------
// RMSNorm -> fp32 (+ optional bf16 pair)
// ---------------------------------------------------------------------------
template<int WB>
__global__ void __launch_bounds__(256) rmsnorm_kernel(
    const float* __restrict__ x, const float* __restrict__ w,
    float* __restrict__ of, __nv_bfloat16* __restrict__ oh,
    __nv_bfloat16* __restrict__ ol)
{
    long row = blockIdx.x;
    const float* xr = x + row * D_DIM;
    int tid = threadIdx.x;

    float s = 0.f;
#pragma unroll
    for (int d = 0; d < 4; d++) {
        float v = xr[tid + d * 256];
        s += v * v;
    }
#pragma unroll
    for (int o = 16; o > 0; o >>= 1) s += __shfl_xor_sync(0xffffffffu, s, o);

    __shared__ float red[8];
    __shared__ float s_inv;
    if ((tid & 31) == 0) red[tid >> 5] = s;
    __syncthreads();
    if (tid == 0) {
        float t = 0.f;
#pragma unroll
        for (int i = 0; i < 8; i++) t += red[i];
        s_inv = 1.0f / (sqrtf(t / (float)D_DIM) + 1e-8f);
    }
    __syncthreads();
    float inv = s_inv;
#pragma unroll
    for (int d = 0; d < 4; d++) {
        int c = tid + d * 256;
        float v = w[c] * xr[c] * inv;
        of[row * D_DIM + c] = v;
        if (WB) bsplit_store(oh, ol, row * D_DIM + c, v);
    }
}

// ---------------------------------------------------------------------------
// Token-shift mixing: fp32 in, two bf16 pairs out
// ---------------------------------------------------------------------------
__global__ void __launch_bounds__(256) mix2_kernel(
    const float* __restrict__ h,
    const float* __restrict__ mA, const float* __restrict__ mB,
    __nv_bfloat16* __restrict__ oAh, __nv_bfloat16* __restrict__ oAl,
    __nv_bfloat16* __restrict__ oBh, __nv_bfloat16* __restrict__ oBl)
{
    long row = blockIdx.x;
    long t = row & (S_LEN - 1);
    long prev = (t == 0) ? row : row - 1;
    int tid = threadIdx.x;
#pragma unroll
    for (int d = 0; d < 4; d++) {
        int c = tid + d * 256;
        long ci = row * D_DIM + c;
        float cur = h[ci];
        float pv  = h[prev * D_DIM + c];
        float a = mA[c], b = mB[c];
        bsplit_store(oAh, oAl, ci, cur * a + pv * (1.f - a));
        bsplit_store(oBh, oBl, ci, cur * b + pv * (1.f - b));
    }
}

// ---------------------------------------------------------------------------
// Sparse attention: top-32, softmax, attn@V (fp32 in) -> bf16 pair out
// ---------------------------------------------------------------------------
__global__ void __launch_bounds__(256) sparse_attn_kernel(
    const float* __restrict__ scores, const float* __restrict__ V,
    __nv_bfloat16* __restrict__ oh, __nv_bfloat16* __restrict__ ol)
{
    __shared__ float sc[S_LEN];
    __shared__ float selV[TOPK];
    __shared__ int   selI[TOPK];
    __shared__ float rv[8];
    __shared__ int   ri[8];
    __shared__ float wsel[TOPK];

    long row = blockIdx.x;
    long b = row >> 12;
    int tid = threadIdx.x;

    const float* srow = scores + row * S_LEN;
    for (int i = tid; i < S_LEN; i += 256) sc[i] = srow[i];
    __syncthreads();

    for (int it = 0; it < TOPK; it++) {
        float bv = NEG_INF;
        int bi = 0x7fffffff;
        for (int i = tid; i < S_LEN; i += 256) {
            float v = sc[i];
            if (v > bv || (v == bv && i < bi)) { bv = v; bi = i; }
        }
#pragma unroll
        for (int o = 16; o > 0; o >>= 1) {
            float ov = __shfl_down_sync(0xffffffffu, bv, o);
            int   oi = __shfl_down_sync(0xffffffffu, bi, o);
            if (ov > bv || (ov == bv && oi < bi)) { bv = ov; bi = oi; }
        }
        if ((tid & 31) == 0) { rv[tid >> 5] = bv; ri[tid >> 5] = bi; }
        __syncthreads();
        if (tid == 0) {
            float fv = rv[0]; int fi = ri[0];
#pragma unroll
            for (int w = 1; w < 8; w++) {
                if (rv[w] > fv || (rv[w] == fv && ri[w] < fi)) { fv = rv[w]; fi = ri[w]; }
            }
            selV[it] = fv; selI[it] = fi;
            sc[fi] = NEG_INF;
        }
        __syncthreads();
    }

    if (tid < TOPK) {
        float m = selV[0];
        float e = expf(selV[tid] - m);
        float s = e;
#pragma unroll
        for (int o = 16; o > 0; o >>= 1) s += __shfl_xor_sync(0xffffffffu, s, o);
        wsel[tid] = e / s;
    }
    __syncthreads();

    float acc[4] = {0.f, 0.f, 0.f, 0.f};
    const float* Vb = V + b * (long)S_LEN * D_DIM;
#pragma unroll 1
    for (int j = 0; j < TOPK; j++) {
        float w = wsel[j];
        const float* vr = Vb + (long)selI[j] * D_DIM;
#pragma unroll
        for (int d = 0; d < 4; d++) acc[d] += w * vr[tid + d * 256];
    }
#pragma unroll
    for (int d = 0; d < 4; d++)
        bsplit_store(oh, ol, row * D_DIM + tid + d * 256, acc[d]);
}

// ---------------------------------------------------------------------------
// Host launchers
// ---------------------------------------------------------------------------
typedef __nv_bfloat16 bf16;

static void launch_bf(int mode,
    const bf16* Ah, const bf16* Al, const bf16* Bh, const bf16* Bl,
    const float* b1, const float* e1, const float* e2,
    float* Of, bf16* Oh, bf16* Ol, int M, int N, int K)
{
    dim3 grid(N / 128, M / 128, 1);
    switch (mode) {
    case 0: gemm_bf<0><<<grid, 256, BF_DSMEM>>>(Ah,Al,Bh,Bl,b1,e1,e2,Of,Oh,Ol,M,N,K); break;
    case 1: gemm_bf<1><<<grid, 256, BF_DSMEM>>>(Ah,Al,Bh,Bl,b1,e1,e2,Of,Oh,Ol,M,N,K); break;
    case 3: gemm_bf<3><<<grid, 256, BF_DSMEM>>>(Ah,Al,Bh,Bl,b1,e1,e2,Of,Oh,Ol,M,N,K); break;
    case 4: gemm_bf<4><<<grid, 256, BF_DSMEM>>>(Ah,Al,Bh,Bl,b1,e1,e2,Of,Oh,Ol,M,N,K); break;
    default: gemm_bf<5><<<grid, 256, BF_DSMEM>>>(Ah,Al,Bh,Bl,b1,e1,e2,Of,Oh,Ol,M,N,K); break;
    }
}

extern "C" void kernel_launch(void* const* d_in, const int* in_sizes, int n_in,
                              void* d_out, int out_size)
{
    const float* x         = (const float*)d_in[0];
    const float* norm1_w   = (const float*)d_in[1];
    const float* tm_mix_v  = (const float*)d_in[3];
    const float* tm_mix_r  = (const float*)d_in[4];
    const float* tm_value_w  = (const float*)d_in[6];
    const float* tm_recept_w = (const float*)d_in[7];
    const float* tm_out_w    = (const float*)d_in[8];
    const float* sa_q_w    = (const float*)d_in[9];
    const float* sa_q_b    = (const float*)d_in[10];
    const float* sa_k_w    = (const float*)d_in[11];
    const float* sa_k_b    = (const float*)d_in[12];
    const float* sa_v_w    = (const float*)d_in[13];
    const float* sa_v_b    = (const float*)d_in[14];
    const float* sa_o_w    = (const float*)d_in[15];
    const float* sa_o_b    = (const float*)d_in[16];
    const float* norm2_w   = (const float*)d_in[17];
    const float* cm_mix_k  = (const float*)d_in[18];
    const float* cm_mix_r  = (const float*)d_in[19];
    const float* cm_key_w    = (const float*)d_in[20];
    const float* cm_recept_w = (const float*)d_in[21];
    const float* cm_value_w  = (const float*)d_in[22];
    float* out = (float*)d_out;

    cudaFuncSetAttribute(gemm_bf<0>, cudaFuncAttributeMaxDynamicSharedMemorySize, BF_DSMEM);
    cudaFuncSetAttribute(gemm_bf<1>, cudaFuncAttributeMaxDynamicSharedMemorySize, BF_DSMEM);
    cudaFuncSetAttribute(gemm_bf<3>, cudaFuncAttributeMaxDynamicSharedMemorySize, BF_DSMEM);
    cudaFuncSetAttribute(gemm_bf<4>, cudaFuncAttributeMaxDynamicSharedMemorySize, BF_DSMEM);
    cudaFuncSetAttribute(gemm_bf<5>, cudaFuncAttributeMaxDynamicSharedMemorySize, BF_DSMEM);
    cudaFuncSetAttribute(gemm_tf<0>, cudaFuncAttributeMaxDynamicSharedMemorySize, TF_DSMEM);
    cudaFuncSetAttribute(gemm_tf<2>, cudaFuncAttributeMaxDynamicSharedMemorySize, TF_DSMEM);

    float* sp = nullptr;
    cudaGetSymbolAddress((void**)&sp, g_scratch);

    float* hF   = sp + O_HF;
    float* Vtm  = sp + O_VTM;
    float* Rtm  = sp + O_RTM;
    float* Vv   = sp + O_VV;
    float* x2   = sp + O_X2;
    float* R2   = sp + O_R2;
    float* Qf   = sp + O_Q;
    float* Kf   = sp + O_K;
    float* wQKf = sp + O_WQKF;
    float* SCo  = sp + O_SC;

    bf16* hbH = (bf16*)(sp + O_BHB); bf16* hbL = (bf16*)(sp + O_BHL);
    bf16* xvH = (bf16*)(sp + O_XVH); bf16* xvL = (bf16*)(sp + O_XVL);
    bf16* xrH = (bf16*)(sp + O_XRH); bf16* xrL = (bf16*)(sp + O_XRL);
    bf16* atH = (bf16*)(sp + O_ATH); bf16* atL = (bf16*)(sp + O_ATL);
    bf16* rkH = (bf16*)(sp + O_RKH); bf16* rkL = (bf16*)(sp + O_RKL);
    bf16* KcH = (bf16*)(sp + O_KCH); bf16* KcL = (bf16*)(sp + O_KCL);

    bf16* wTMVh = (bf16*)(sp + O_WTMV); bf16* wTMVl = wTMVh + 1048576L;
    bf16* wTMRh = (bf16*)(sp + O_WTMR); bf16* wTMRl = wTMRh + 1048576L;
    bf16* wSAVh = (bf16*)(sp + O_WSAV); bf16* wSAVl = wSAVh + 1048576L;
    bf16* wSAOh = (bf16*)(sp + O_WSAO); bf16* wSAOl = wSAOh + 1048576L;
    bf16* wTMOh = (bf16*)(sp + O_WTMO); bf16* wTMOl = wTMOh + 1048576L;
    bf16* wCMRh = (bf16*)(sp + O_WCMR); bf16* wCMRl = wCMRh + 1048576L;
    bf16* wCMKh = (bf16*)(sp + O_WCMK); bf16* wCMKl = wCMKh + 4194304L;
    bf16* wCMVh = (bf16*)(sp + O_WCMV); bf16* wCMVl = wCMVh + 4194304L;

    // weight splits
    split_bf<<<2048, 256>>>(tm_value_w,  wTMVh, wTMVl, 1048576L);
    split_bf<<<2048, 256>>>(tm_recept_w, wTMRh, wTMRl, 1048576L);
    split_bf<<<2048, 256>>>(sa_v_w,      wSAVh, wSAVl, 1048576L);
    split_bf<<<2048, 256>>>(sa_o_w,      wSAOh, wSAOl, 1048576L);
    split_bf<<<2048, 256>>>(tm_out_w,    wTMOh, wTMOl, 1048576L);
    split_bf<<<2048, 256>>>(cm_recept_w, wCMRh, wCMRl, 1048576L);
    split_bf<<<8192, 256>>>(cm_key_w,    wCMKh, wCMKl, 4194304L);
    split_bf<<<8192, 256>>>(cm_value_w,  wCMVh, wCMVl, 4194304L);
    concat_qk<<<512, 256>>>(sa_q_w, sa_k_w, wQKf);

    // --- time-mix branch ---
    rmsnorm_kernel<1><<<NROWS, 256>>>(x, norm1_w, hF, hbH, hbL);
    mix2_kernel<<<NROWS, 256>>>(hF, tm_mix_v, tm_mix_r, xvH, xvL, xrH, xrL);

    launch_bf(0, xvH, xvL, wTMVh, wTMVl, nullptr, nullptr, nullptr,
              Vtm, nullptr, nullptr, NROWS, D_DIM, D_DIM);
    launch_bf(0, xrH, xrL, wTMRh, wTMRl, nullptr, nullptr, nullptr,
              Rtm, nullptr, nullptr, NROWS, D_DIM, D_DIM);

    // Q||K projection on tf32x3 precision path
    {
        dim3 g(1, NROWS / 128, 1);
        gemm_tf<2><<<g, 256, TF_DSMEM>>>(hF, wQKf, sa_q_b, sa_k_b,
                                         nullptr, Qf, Kf, NROWS, 128, D_DIM,
                                         1.f, 0, 0, 0);
    }

    launch_bf(0, hbH, hbL, wSAVh, wSAVl, sa_v_b, nullptr, nullptr,
              Vv, nullptr, nullptr, NROWS, D_DIM, D_DIM);

    // scores[b] = (Q[b] @ K[b]^T) / 8 on tf32x3
    {
        dim3 g(S_LEN / 128, S_LEN / 128, B_SZ);
        gemm_tf<0><<<g, 256, TF_DSMEM>>>(Qf, Kf, nullptr, nullptr,
                                         SCo, nullptr, nullptr, S_LEN, S_LEN, A_DIM,
                                         0.125f, (long)S_LEN * A_DIM,
                                         (long)S_LEN * A_DIM, (long)S_LEN * S_LEN);
    }

    sparse_attn_kernel<<<NROWS, 256>>>(SCo, Vv, atH, atL);

    // rkv = sigmoid(Rtm) * (attn@W_o + b_o + Vtm) -> bf16 pair
    launch_bf(3, atH, atL, wSAOh, wSAOl, sa_o_b, Rtm, Vtm,
              nullptr, rkH, rkL, NROWS, D_DIM, D_DIM);

    // x2 = x + rkv @ W_out
    launch_bf(4, rkH, rkL, wTMOh, wTMOl, nullptr, x, nullptr,
              x2, nullptr, nullptr, NROWS, D_DIM, D_DIM);

    // --- channel-mix branch ---
    rmsnorm_kernel<0><<<NROWS, 256>>>(x2, norm2_w, hF, nullptr, nullptr);
    mix2_kernel<<<NROWS, 256>>>(hF, cm_mix_k, cm_mix_r, xvH, xvL, xrH, xrL);

    // Kc = relu(xk2 @ W_k)^2 -> bf16 pair
    launch_bf(1, xvH, xvL, wCMKh, wCMKl, nullptr, nullptr, nullptr,
              nullptr, KcH, KcL, NROWS, DI_DIM, D_DIM);
    launch_bf(0, xrH, xrL, wCMRh, wCMRl, nullptr, nullptr, nullptr,
              R2, nullptr, nullptr, NROWS, D_DIM, D_DIM);

    // out = x2 + sigmoid(R2) * (Kc @ W_v)
    launch_bf(5, KcH, KcL, wCMVh, wCMVl, nullptr, x2, R2,
              out, nullptr, nullptr, NROWS, D_DIM, DI_DIM);
}

// round 10
// speedup vs baseline: 2.1509x; 1.1564x over previous
#include <cuda_runtime.h>
#include <cuda_bf16.h>
#include <math.h>
#include <stdint.h>

// Problem constants
#define D_DIM   1024
#define S_LEN   4096
#define B_SZ    2
#define A_DIM   64
#define DI_DIM  4096
#define TOPK    32
#define NROWS   (B_SZ * S_LEN)                 // 8192
#define ROWELEMS ((long)NROWS * D_DIM)         // 8,388,608

#define NEG_INF (-3.402823466e38f)

// ---------------------------------------------------------------------------
// Scratch layout (float offsets; bf16 arrays overlay pairs of floats)
// ---------------------------------------------------------------------------
static const long O_HF   = 0L;
static const long O_VTM  = 8388608L;
static const long O_RTM  = 16777216L;
static const long O_VV   = 25165824L;
static const long O_X2   = 33554432L;
static const long O_R2   = 41943040L;
static const long O_Q    = 50331648L;   // 524288 fp32
static const long O_K    = 50855936L;   // 524288 fp32
static const long O_WQKF = 51380224L;   // 131072 fp32 (concat q/k weights)
static const long O_SC   = 51511296L;   // 33554432 fp32
// bf16 arrays (float-offset; each float slot holds 2 bf16)
static const long O_BHB = 85065728L;
static const long O_BHL = 89260032L;
static const long O_XVH = 93454336L;
static const long O_XVL = 97648640L;
static const long O_XRH = 101842944L;
static const long O_XRL = 106037248L;
static const long O_ATH = 110231552L;
static const long O_ATL = 114425856L;
static const long O_RKH = 118620160L;
static const long O_RKL = 122814464L;
static const long O_KCH = 127008768L;
static const long O_KCL = 143785984L;
static const long O_WB  = 160563200L;
static const long O_WTMV = O_WB;
static const long O_WTMR = O_WTMV + 1048576L;
static const long O_WSAV = O_WTMR + 1048576L;
static const long O_WSAO = O_WSAV + 1048576L;
static const long O_WTMO = O_WSAO + 1048576L;
static const long O_WCMR = O_WTMO + 1048576L;
static const long O_WCMK = O_WCMR + 1048576L;
static const long O_WCMV = O_WCMK + 4194304L;
// end = O_WCMV + 4194304 = 175243264

__device__ __align__(16) float g_scratch[175243264];

// ===========================================================================
// helpers
// ===========================================================================
__device__ __forceinline__ uint32_t smem_u32(const void* p) {
    uint32_t a;
    asm("{ .reg .u64 t; cvta.to.shared.u64 t, %1; cvt.u32.u64 %0, t; }"
        : "=r"(a) : "l"(p));
    return a;
}
__device__ __forceinline__ uint32_t f2tf32(float x) {
    uint32_t r;
    asm("cvt.rna.tf32.f32 %0, %1;" : "=r"(r) : "f"(x));
    return r;
}
__device__ __forceinline__ void split_tf32(uint32_t xbits, uint32_t& hi, uint32_t& lo) {
    float x = __uint_as_float(xbits);
    hi = f2tf32(x);
    lo = f2tf32(x - __uint_as_float(hi));
}
__device__ __forceinline__ float sigmoidf_(float x) { return 1.f / (1.f + expf(-x)); }

__device__ __forceinline__ void cp16(uint32_t s, const void* g) {
    asm volatile("cp.async.cg.shared.global [%0], [%1], 16;" :: "r"(s), "l"(g));
}

// scalar bf16 hi/lo split store
__device__ __forceinline__ void bsplit_store(__nv_bfloat16* H, __nv_bfloat16* L,
                                             long i, float v) {
    __nv_bfloat16 h = __float2bfloat16(v);
    H[i] = h;
    L[i] = __float2bfloat16(v - __bfloat162float(h));
}
__device__ __forceinline__ void bpair_store(__nv_bfloat16* H, __nv_bfloat16* L,
                                            long idx, float vx, float vy) {
    __nv_bfloat16 hx = __float2bfloat16(vx);
    __nv_bfloat16 hy = __float2bfloat16(vy);
    __nv_bfloat16 lx = __float2bfloat16(vx - __bfloat162float(hx));
    __nv_bfloat16 ly = __float2bfloat16(vy - __bfloat162float(hy));
    __nv_bfloat162 hp; hp.x = hx; hp.y = hy;
    __nv_bfloat162 lp; lp.x = lx; lp.y = ly;
    *(__nv_bfloat162*)(H + idx) = hp;
    *(__nv_bfloat162*)(L + idx) = lp;
}

__device__ __forceinline__ void mma1688(float* c, const uint32_t* a, const uint32_t* b) {
    asm volatile(
        "mma.sync.aligned.m16n8k8.row.col.f32.tf32.tf32.f32 "
        "{%0,%1,%2,%3}, {%4,%5,%6,%7}, {%8,%9}, {%0,%1,%2,%3};"
        : "+f"(c[0]), "+f"(c[1]), "+f"(c[2]), "+f"(c[3])
        : "r"(a[0]), "r"(a[1]), "r"(a[2]), "r"(a[3]), "r"(b[0]), "r"(b[1]));
}
__device__ __forceinline__ void mma16816(float* c, const uint32_t* a, const uint32_t* b) {
    asm volatile(
        "mma.sync.aligned.m16n8k16.row.col.f32.bf16.bf16.f32 "
        "{%0,%1,%2,%3}, {%4,%5,%6,%7}, {%8,%9}, {%0,%1,%2,%3};"
        : "+f"(c[0]), "+f"(c[1]), "+f"(c[2]), "+f"(c[3])
        : "r"(a[0]), "r"(a[1]), "r"(a[2]), "r"(a[3]), "r"(b[0]), "r"(b[1]));
}
__device__ __forceinline__ void ldm_x4(uint32_t* r, uint32_t a) {
    asm volatile("ldmatrix.sync.aligned.m8n8.x4.shared.b16 {%0,%1,%2,%3}, [%4];"
        : "=r"(r[0]), "=r"(r[1]), "=r"(r[2]), "=r"(r[3]) : "r"(a));
}

// ===========================================================================
// bf16x3 GEMM (NT): C = (Ah+Al)(Bh+Bl)^T via al*bh + ah*bl + ah*bh
// BM=BN=128, BK=32 bf16, 3-stage cp.async, 256 thr, warp 2m x 4n, 64x32 tile.
// Tiles [128 rows][64B], 16B-granule XOR swizzle; fragments via ldmatrix.x4.
// MODEs: 0: Of = acc (+bias1)     1: relu(acc)^2 -> (Oh,Ol)
//        3: sigmoid(ex1)*(acc+bias1+ex2) -> (Oh,Ol)
//        4: Of = ex1 + acc        5: Of = ex1 + sigmoid(ex2)*acc
// ===========================================================================
#define BTILE 8192                    // 128*32*2
#define BSTG  (4 * BTILE)             // 32768
#define BNSTG 3
#define BF_DSMEM (BNSTG * BSTG + 128) // 98432 (pad for 128B alignment)

__device__ __forceinline__ void load_stage_bf(
    uint32_t sbase, int stage,
    const __nv_bfloat16* __restrict__ Ah, const __nv_bfloat16* __restrict__ Al,
    const __nv_bfloat16* __restrict__ Bh, const __nv_bfloat16* __restrict__ Bl,
    int bm, int bn, int k0, int K, int tid)
{
    uint32_t s = sbase + stage * BSTG;
#pragma unroll
    for (int j = 0; j < 2; j++) {
        int gi = tid + j * 256;        // 0..511
        int row = gi >> 2, g = gi & 3;
        uint32_t so = (uint32_t)(row * 64 + ((g ^ ((row >> 1) & 3)) << 4));
        long ao = (long)(bm + row) * K + k0 + g * 8;
        long bo = (long)(bn + row) * K + k0 + g * 8;
        cp16(s + so,             Ah + ao);
        cp16(s + BTILE + so,     Al + ao);
        cp16(s + 2 * BTILE + so, Bh + bo);
        cp16(s + 3 * BTILE + so, Bl + bo);
    }
}

template<int MODE>
__global__ void __launch_bounds__(256, 2) gemm_bf(
    const __nv_bfloat16* __restrict__ Ah, const __nv_bfloat16* __restrict__ Al,
    const __nv_bfloat16* __restrict__ Bh, const __nv_bfloat16* __restrict__ Bl,
    const float* __restrict__ bias1,
    const float* __restrict__ ex1, const float* __restrict__ ex2,
    float* __restrict__ Of,
    __nv_bfloat16* __restrict__ Oh, __nv_bfloat16* __restrict__ Ol,
    int M, int N, int K)
{
    extern __shared__ __align__(16) char dsm[];

    const int tid  = threadIdx.x;
    const int wid  = tid >> 5;
    const int lane = tid & 31;
    const int wm   = wid & 1;
    const int wn   = wid >> 1;
    const int bm = blockIdx.y * 128;
    const int bn = blockIdx.x * 128;
    const int KT = K / 32;
    const int lr = lane >> 2, lk = lane & 3;

    float acc[4][4][4];
#pragma unroll
    for (int i = 0; i < 4; i++)
#pragma unroll
        for (int j = 0; j < 4; j++)
#pragma unroll
            for (int r = 0; r < 4; r++) acc[i][j][r] = 0.f;

    // ldmatrix per-lane swizzled offsets (granule bit from lane>>4)
    uint32_t offAh[4], offAl[4], offBh[2], offBl[2];
    {
        int ga = (lane >> 4) & 1;
        int rb = wm * 64 + (lane & 15);
#pragma unroll
        for (int mf = 0; mf < 4; mf++) {
            int row = rb + mf * 16;
            uint32_t o = (uint32_t)(row * 64 + ((ga ^ ((row >> 1) & 3)) << 4));
            offAh[mf] = o;
            offAl[mf] = o + BTILE;
        }
#pragma unroll
        for (int pg = 0; pg < 2; pg++) {
            int row = wn * 32 + pg * 16 + (lane & 15);
            uint32_t o = (uint32_t)(row * 64 + ((ga ^ ((row >> 1) & 3)) << 4));
            offBh[pg] = o + 2 * BTILE;
            offBl[pg] = o + 3 * BTILE;
        }
    }

    uint32_t sbase = (smem_u32(dsm) + 127u) & ~127u;
    load_stage_bf(sbase, 0, Ah, Al, Bh, Bl, bm, bn, 0, K, tid);
    asm volatile("cp.async.commit_group;" ::: "memory");
    load_stage_bf(sbase, 1, Ah, Al, Bh, Bl, bm, bn, 32, K, tid);
    asm volatile("cp.async.commit_group;" ::: "memory");

    int stage = 0;
    for (int kt = 0; kt < KT; kt++) {
        int ps = kt + 2;
        if (ps < KT) {
            int pstage = stage + 2; if (pstage >= BNSTG) pstage -= BNSTG;
            load_stage_bf(sbase, pstage, Ah, Al, Bh, Bl, bm, bn, ps * 32, K, tid);
        }
        asm volatile("cp.async.commit_group;" ::: "memory");
        asm volatile("cp.async.wait_group 2;" ::: "memory");
        __syncthreads();

        uint32_t st = sbase + stage * BSTG;

#pragma unroll
        for (int ks = 0; ks < 2; ks++) {
            uint32_t kx = (uint32_t)(ks << 5);
            uint32_t ah[4][4], al[4][4];
#pragma unroll
            for (int mf = 0; mf < 4; mf++) {
                ldm_x4(ah[mf], (st + offAh[mf]) ^ kx);
                ldm_x4(al[mf], (st + offAl[mf]) ^ kx);
            }
#pragma unroll
            for (int pg = 0; pg < 2; pg++) {
                uint32_t tb[4], tl[4];
                ldm_x4(tb, (st + offBh[pg]) ^ kx);
                ldm_x4(tl, (st + offBl[pg]) ^ kx);
                uint32_t b0h[2] = {tb[0], tb[2]};
                uint32_t b1h[2] = {tb[1], tb[3]};
                uint32_t b0l[2] = {tl[0], tl[2]};
                uint32_t b1l[2] = {tl[1], tl[3]};
                int nf0 = pg * 2, nf1 = pg * 2 + 1;
#pragma unroll
                for (int mf = 0; mf < 4; mf++) {
                    mma16816(acc[mf][nf0], al[mf], b0h);
                    mma16816(acc[mf][nf0], ah[mf], b0l);
                    mma16816(acc[mf][nf0], ah[mf], b0h);
                    mma16816(acc[mf][nf1], al[mf], b1h);
                    mma16816(acc[mf][nf1], ah[mf], b1l);
                    mma16816(acc[mf][nf1], ah[mf], b1h);
                }
            }
        }
        __syncthreads();
        stage++; if (stage >= BNSTG) stage = 0;
    }

    // epilogue
#pragma unroll
    for (int mf = 0; mf < 4; mf++) {
        int r0 = bm + wm * 64 + mf * 16 + lr;
#pragma unroll
        for (int nf = 0; nf < 4; nf++) {
            int c0 = bn + wn * 32 + nf * 8 + lk * 2;
#pragma unroll
            for (int h = 0; h < 2; h++) {
                int row = r0 + h * 8;
                long idx = (long)row * N + c0;
                float vx = acc[mf][nf][2 * h + 0];
                float vy = acc[mf][nf][2 * h + 1];
                if (MODE == 0) {
                    if (bias1) { vx += bias1[c0]; vy += bias1[c0 + 1]; }
                    *(float2*)(Of + idx) = make_float2(vx, vy);
                } else if (MODE == 1) {
                    vx = fmaxf(vx, 0.f); vx *= vx;
                    vy = fmaxf(vy, 0.f); vy *= vy;
                    bpair_store(Oh, Ol, idx, vx, vy);
                } else if (MODE == 3) {
                    vx += bias1[c0]; vy += bias1[c0 + 1];
                    float rx = sigmoidf_(ex1[idx])     * (vx + ex2[idx]);
                    float ry = sigmoidf_(ex1[idx + 1]) * (vy + ex2[idx + 1]);
                    bpair_store(Oh, Ol, idx, rx, ry);
                } else if (MODE == 4) {
                    *(float2*)(Of + idx) = make_float2(ex1[idx] + vx, ex1[idx + 1] + vy);
                } else { // 5
                    float rx = ex1[idx]     + sigmoidf_(ex2[idx])     * vx;
                    float ry = ex1[idx + 1] + sigmoidf_(ex2[idx + 1]) * vy;
                    *(float2*)(Of + idx) = make_float2(rx, ry);
                }
            }
        }
    }
}

// ===========================================================================
// tf32x3 GEMM (NT) with in-kernel split (fp32 inputs) — precision path.
// MODEs: 0: O1 = alpha*acc (batched via blockIdx.z strides)
//        2: QK: col<64 -> Qf=acc+qb, col>=64 -> Kf=acc+kb (fp32 [row][64])
// ===========================================================================
#define TBKF 16
#define T_A_BYTES (128 * TBKF * 4)      // 8192
#define T_STG     (2 * T_A_BYTES)       // 16384
#define TNSTG 4
#define TF_DSMEM (TNSTG * T_STG)        // 65536

__device__ __forceinline__ uint32_t lde(const uint32_t* t, int row, int k) {
    int g = k >> 2;
    return t[row * 16 + (((g ^ ((row >> 1) & 3)) << 2) | (k & 3))];
}

__device__ __forceinline__ void load_stage_tf(
    uint32_t sbase, int stage, const float* __restrict__ A,
    const float* __restrict__ B, int bm, int bn, int k0, int K, int tid)
{
    uint32_t sa = sbase + stage * T_STG;
    uint32_t sb = sa + T_A_BYTES;
    int row = tid >> 1;
    int g0 = (tid & 1) * 2;
#pragma unroll
    for (int j = 0; j < 2; j++) {
        int g = g0 + j;
        uint32_t so = (uint32_t)(row * 64 + ((g ^ ((row >> 1) & 3)) << 4));
        cp16(sa + so, A + (long)(bm + row) * K + k0 + g * 4);
        cp16(sb + so, B + (long)(bn + row) * K + k0 + g * 4);
    }
}

template<int MODE>
__global__ void __launch_bounds__(256) gemm_tf(
    const float* __restrict__ A, const float* __restrict__ B,
    const float* __restrict__ qb, const float* __restrict__ kb,
    float* __restrict__ O1, float* __restrict__ Qf, float* __restrict__ Kf,
    int M, int N, int K, float alpha, long sA, long sB, long sC)
{
    extern __shared__ __align__(16) char dsm[];

    A += (long)blockIdx.z * sA;
    B += (long)blockIdx.z * sB;
    O1 += (long)blockIdx.z * sC;

    const int tid  = threadIdx.x;
    const int wid  = tid >> 5;
    const int lane = tid & 31;
    const int wm   = wid & 1;
    const int wn   = wid >> 1;
    const int bm = blockIdx.y * 128;
    const int bn = blockIdx.x * 128;
    const int KT = K / TBKF;

    uint32_t sbase = smem_u32(dsm);

    float acc[4][4][4];
#pragma unroll
    for (int i = 0; i < 4; i++)
#pragma unroll
        for (int j = 0; j < 4; j++)
#pragma unroll
            for (int r = 0; r < 4; r++) acc[i][j][r] = 0.f;

#pragma unroll
    for (int s = 0; s < TNSTG - 1; s++) {
        if (s < KT) load_stage_tf(sbase, s, A, B, bm, bn, s * TBKF, K, tid);
        asm volatile("cp.async.commit_group;" ::: "memory");
    }

    const int lr = lane >> 2;
    const int lk = lane & 3;

    for (int kt = 0; kt < KT; kt++) {
        __syncthreads();
        if (kt + 3 < KT)
            load_stage_tf(sbase, (kt + 3) & 3, A, B, bm, bn, (kt + 3) * TBKF, K, tid);
        asm volatile("cp.async.commit_group;" ::: "memory");
        asm volatile("cp.async.wait_group 3;" ::: "memory");
        __syncthreads();

        const uint32_t* sa = (const uint32_t*)(dsm + (size_t)(kt & 3) * T_STG);
        const uint32_t* sb = sa + 128 * TBKF;

#pragma unroll
        for (int ks = 0; ks < 2; ks++) {
            int kbase = ks * 8;
            uint32_t ah[4][4], al[4][4], bh[4][2], bl[4][2];
#pragma unroll
            for (int mf = 0; mf < 4; mf++) {
                int r0 = wm * 64 + mf * 16 + lr;
                split_tf32(lde(sa, r0,     kbase + lk),     ah[mf][0], al[mf][0]);
                split_tf32(lde(sa, r0 + 8, kbase + lk),     ah[mf][1], al[mf][1]);
                split_tf32(lde(sa, r0,     kbase + lk + 4), ah[mf][2], al[mf][2]);
                split_tf32(lde(sa, r0 + 8, kbase + lk + 4), ah[mf][3], al[mf][3]);
            }
#pragma unroll
            for (int nf = 0; nf < 4; nf++) {
                int n0 = wn * 32 + nf * 8 + lr;
                split_tf32(lde(sb, n0, kbase + lk),     bh[nf][0], bl[nf][0]);
                split_tf32(lde(sb, n0, kbase + lk + 4), bh[nf][1], bl[nf][1]);
            }
#pragma unroll
            for (int mf = 0; mf < 4; mf++)
#pragma unroll
                for (int nf = 0; nf < 4; nf++) {
                    mma1688(acc[mf][nf], al[mf], bh[nf]);
                    mma1688(acc[mf][nf], ah[mf], bl[nf]);
                    mma1688(acc[mf][nf], ah[mf], bh[nf]);
                }
        }
    }

#pragma unroll
    for (int mf = 0; mf < 4; mf++) {
        int r0 = bm + wm * 64 + mf * 16 + lr;
#pragma unroll
        for (int nf = 0; nf < 4; nf++) {
            int c0 = bn + wn * 32 + nf * 8 + lk * 2;
#pragma unroll
            for (int h = 0; h < 2; h++) {
                int row = r0 + h * 8;
                float vx = acc[mf][nf][2 * h + 0] * alpha;
                float vy = acc[mf][nf][2 * h + 1] * alpha;
                if (MODE == 0) {
                    *(float2*)(O1 + (long)row * N + c0) = make_float2(vx, vy);
                } else { // MODE 2: Q||K
                    if (c0 < 64) {
                        vx += qb[c0]; vy += qb[c0 + 1];
                        *(float2*)(Qf + (long)row * 64 + c0) = make_float2(vx, vy);
                    } else {
                        vx += kb[c0 - 64]; vy += kb[c0 - 63];
                        *(float2*)(Kf + (long)row * 64 + c0 - 64) = make_float2(vx, vy);
                    }
                }
            }
        }
    }
}

// ---------------------------------------------------------------------------
// Weight splits: fp32 -> bf16 hi/lo (fused batches)
// ---------------------------------------------------------------------------
struct SplitJob { const float* src; __nv_bfloat16* h; __nv_bfloat16* l; };
struct SplitJobs6 { SplitJob j[6]; };
struct SplitJobs2 { SplitJob j[2]; };

__global__ void __launch_bounds__(256) split6(SplitJobs6 jobs, long n)
{
    const SplitJob jb = jobs.j[blockIdx.y];
    long i = ((long)blockIdx.x * 256 + threadIdx.x) * 2;
    if (i < n) bpair_store(jb.h, jb.l, i, jb.src[i], jb.src[i + 1]);
}
__global__ void __launch_bounds__(256) split2(SplitJobs2 jobs, long n)
{
    const SplitJob jb = jobs.j[blockIdx.y];
    long i = ((long)blockIdx.x * 256 + threadIdx.x) * 2;
    if (i < n) bpair_store(jb.h, jb.l, i, jb.src[i], jb.src[i + 1]);
}

__global__ void __launch_bounds__(256) concat_qk(
    const float* __restrict__ q, const float* __restrict__ k, float* __restrict__ o)
{
    int i = blockIdx.x * 256 + threadIdx.x;   // n = 131072
    o[i] = (i < 65536) ? q[i] : k[i - 65536];
}

// ---------------------------------------------------------------------------
// RMSNorm -> fp32 (+ optional bf16 pair)
// ---------------------------------------------------------------------------
template<int WB>
__global__ void __launch_bounds__(256) rmsnorm_kernel(
    const float* __restrict__ x, const float* __restrict__ w,
    float* __restrict__ of, __nv_bfloat16* __restrict__ oh,
    __nv_bfloat16* __restrict__ ol)
{
    long row = blockIdx.x;
    const float* xr = x + row * D_DIM;
    int tid = threadIdx.x;

    float s = 0.f;
#pragma unroll
    for (int d = 0; d < 4; d++) {
        float v = xr[tid + d * 256];
        s += v * v;
    }
#pragma unroll
    for (int o = 16; o > 0; o >>= 1) s += __shfl_xor_sync(0xffffffffu, s, o);

    __shared__ float red[8];
    __shared__ float s_inv;
    if ((tid & 31) == 0) red[tid >> 5] = s;
    __syncthreads();
    if (tid == 0) {
        float t = 0.f;
#pragma unroll
        for (int i = 0; i < 8; i++) t += red[i];
        s_inv = 1.0f / (sqrtf(t / (float)D_DIM) + 1e-8f);
    }
    __syncthreads();
    float inv = s_inv;
#pragma unroll
    for (int d = 0; d < 4; d++) {
        int c = tid + d * 256;
        float v = w[c] * xr[c] * inv;
        of[row * D_DIM + c] = v;
        if (WB) bsplit_store(oh, ol, row * D_DIM + c, v);
    }
}

// ---------------------------------------------------------------------------
// Token-shift mixing: fp32 in, two bf16 pairs out
// ---------------------------------------------------------------------------
__global__ void __launch_bounds__(256) mix2_kernel(
    const float* __restrict__ h,
    const float* __restrict__ mA, const float* __restrict__ mB,
    __nv_bfloat16* __restrict__ oAh, __nv_bfloat16* __restrict__ oAl,
    __nv_bfloat16* __restrict__ oBh, __nv_bfloat16* __restrict__ oBl)
{
    long row = blockIdx.x;
    long t = row & (S_LEN - 1);
    long prev = (t == 0) ? row : row - 1;
    int tid = threadIdx.x;
#pragma unroll
    for (int d = 0; d < 4; d++) {
        int c = tid + d * 256;
        long ci = row * D_DIM + c;
        float cur = h[ci];
        float pv  = h[prev * D_DIM + c];
        float a = mA[c], b = mB[c];
        bsplit_store(oAh, oAl, ci, cur * a + pv * (1.f - a));
        bsplit_store(oBh, oBl, ci, cur * b + pv * (1.f - b));
    }
}

// ---------------------------------------------------------------------------
// Sparse attention: chunked top-32, softmax, attn@V -> bf16 pair out.
// One block (256 thr) per query row. Chunk maxima (128 chunks of 32) make
// each of the 32 selection rounds O(128 + 32) instead of O(4096).
// ---------------------------------------------------------------------------
__global__ void __launch_bounds__(256) sparse_attn_kernel(
    const float* __restrict__ scores, const float* __restrict__ V,
    __nv_bfloat16* __restrict__ oh, __nv_bfloat16* __restrict__ ol)
{
    __shared__ float sc[S_LEN];
    __shared__ float cmax[128];
    __shared__ float selV[TOPK];
    __shared__ int   selI[TOPK];
    __shared__ float wsel[TOPK];

    long row = blockIdx.x;
    long b = row >> 12;
    int tid = threadIdx.x;
    int lane = tid & 31;

    const float* srow = scores + row * S_LEN;
    for (int i = tid; i < S_LEN; i += 256) sc[i] = srow[i];
    __syncthreads();

    if (tid < 128) {
        float m = NEG_INF;
#pragma unroll 8
        for (int i = 0; i < 32; i++) m = fmaxf(m, sc[tid * 32 + i]);
        cmax[tid] = m;
    }
    __syncthreads();

    if (tid < 32) {   // warp 0 runs selection
        for (int it = 0; it < TOPK; it++) {
            // 1) best chunk (value desc, chunk asc)
            float bv = NEG_INF; int bc = 0;
#pragma unroll
            for (int j = 0; j < 4; j++) {
                int c = lane * 4 + j;
                float v = cmax[c];
                if (v > bv) { bv = v; bc = c; }
            }
#pragma unroll
            for (int o = 16; o > 0; o >>= 1) {
                float ov = __shfl_down_sync(0xffffffffu, bv, o);
                int   oc = __shfl_down_sync(0xffffffffu, bc, o);
                if (ov > bv || (ov == bv && oc < bc)) { bv = ov; bc = oc; }
            }
            bc = __shfl_sync(0xffffffffu, bc, 0);

            // 2) argmax within chunk (value desc, index asc)
            float v = sc[bc * 32 + lane];
            float mv = v; int mi = lane;
#pragma unroll
            for (int o = 16; o > 0; o >>= 1) {
                float ov = __shfl_down_sync(0xffffffffu, mv, o);
                int   oi = __shfl_down_sync(0xffffffffu, mi, o);
                if (ov > mv || (ov == mv && oi < mi)) { mv = ov; mi = oi; }
            }
            mv = __shfl_sync(0xffffffffu, mv, 0);
            mi = __shfl_sync(0xffffffffu, mi, 0);

            if (lane == mi) { sc[bc * 32 + lane] = NEG_INF; v = NEG_INF; }
            if (lane == 0) { selV[it] = mv; selI[it] = bc * 32 + mi; }

            // 3) refresh chunk max
            float nm = v;
#pragma unroll
            for (int o = 16; o > 0; o >>= 1)
                nm = fmaxf(nm, __shfl_down_sync(0xffffffffu, nm, o));
            if (lane == 0) cmax[bc] = nm;
        }
        // softmax over selected (selV[0] is the global max)
        float m = __shfl_sync(0xffffffffu, selV[0], 0);
        float e = expf(selV[lane] - m);
        float s = e;
#pragma unroll
        for (int o = 16; o > 0; o >>= 1) s += __shfl_xor_sync(0xffffffffu, s, o);
        wsel[lane] = e / s;
    }
    __syncthreads();

    float acc[4] = {0.f, 0.f, 0.f, 0.f};
    const float* Vb = V + b * (long)S_LEN * D_DIM;
#pragma unroll 1
    for (int j = 0; j < TOPK; j++) {
        float w = wsel[j];
        const float* vr = Vb + (long)selI[j] * D_DIM;
#pragma unroll
        for (int d = 0; d < 4; d++) acc[d] += w * vr[tid + d * 256];
    }
#pragma unroll
    for (int d = 0; d < 4; d++)
        bsplit_store(oh, ol, row * D_DIM + tid + d * 256, acc[d]);
}

// ---------------------------------------------------------------------------
// Host launchers
// ---------------------------------------------------------------------------
typedef __nv_bfloat16 bf16;

static void launch_bf(int mode,
    const bf16* Ah, const bf16* Al, const bf16* Bh, const bf16* Bl,
    const float* b1, const float* e1, const float* e2,
    float* Of, bf16* Oh, bf16* Ol, int M, int N, int K)
{
    dim3 grid(N / 128, M / 128, 1);
    switch (mode) {
    case 0: gemm_bf<0><<<grid, 256, BF_DSMEM>>>(Ah,Al,Bh,Bl,b1,e1,e2,Of,Oh,Ol,M,N,K); break;
    case 1: gemm_bf<1><<<grid, 256, BF_DSMEM>>>(Ah,Al,Bh,Bl,b1,e1,e2,Of,Oh,Ol,M,N,K); break;
    case 3: gemm_bf<3><<<grid, 256, BF_DSMEM>>>(Ah,Al,Bh,Bl,b1,e1,e2,Of,Oh,Ol,M,N,K); break;
    case 4: gemm_bf<4><<<grid, 256, BF_DSMEM>>>(Ah,Al,Bh,Bl,b1,e1,e2,Of,Oh,Ol,M,N,K); break;
    default: gemm_bf<5><<<grid, 256, BF_DSMEM>>>(Ah,Al,Bh,Bl,b1,e1,e2,Of,Oh,Ol,M,N,K); break;
    }
}

extern "C" void kernel_launch(void* const* d_in, const int* in_sizes, int n_in,
                              void* d_out, int out_size)
{
    const float* x         = (const float*)d_in[0];
    const float* norm1_w   = (const float*)d_in[1];
    const float* tm_mix_v  = (const float*)d_in[3];
    const float* tm_mix_r  = (const float*)d_in[4];
    const float* tm_value_w  = (const float*)d_in[6];
    const float* tm_recept_w = (const float*)d_in[7];
    const float* tm_out_w    = (const float*)d_in[8];
    const float* sa_q_w    = (const float*)d_in[9];
    const float* sa_q_b    = (const float*)d_in[10];
    const float* sa_k_w    = (const float*)d_in[11];
    const float* sa_k_b    = (const float*)d_in[12];
    const float* sa_v_w    = (const float*)d_in[13];
    const float* sa_v_b    = (const float*)d_in[14];
    const float* sa_o_w    = (const float*)d_in[15];
    const float* sa_o_b    = (const float*)d_in[16];
    const float* norm2_w   = (const float*)d_in[17];
    const float* cm_mix_k  = (const float*)d_in[18];
    const float* cm_mix_r  = (const float*)d_in[19];
    const float* cm_key_w    = (const float*)d_in[20];
    const float* cm_recept_w = (const float*)d_in[21];
    const float* cm_value_w  = (const float*)d_in[22];
    float* out = (float*)d_out;

    cudaFuncSetAttribute(gemm_bf<0>, cudaFuncAttributeMaxDynamicSharedMemorySize, BF_DSMEM);
    cudaFuncSetAttribute(gemm_bf<1>, cudaFuncAttributeMaxDynamicSharedMemorySize, BF_DSMEM);
    cudaFuncSetAttribute(gemm_bf<3>, cudaFuncAttributeMaxDynamicSharedMemorySize, BF_DSMEM);
    cudaFuncSetAttribute(gemm_bf<4>, cudaFuncAttributeMaxDynamicSharedMemorySize, BF_DSMEM);
    cudaFuncSetAttribute(gemm_bf<5>, cudaFuncAttributeMaxDynamicSharedMemorySize, BF_DSMEM);
    cudaFuncSetAttribute(gemm_tf<0>, cudaFuncAttributeMaxDynamicSharedMemorySize, TF_DSMEM);
    cudaFuncSetAttribute(gemm_tf<2>, cudaFuncAttributeMaxDynamicSharedMemorySize, TF_DSMEM);

    float* sp = nullptr;
    cudaGetSymbolAddress((void**)&sp, g_scratch);

    float* hF   = sp + O_HF;
    float* Vtm  = sp + O_VTM;
    float* Rtm  = sp + O_RTM;
    float* Vv   = sp + O_VV;
    float* x2   = sp + O_X2;
    float* R2   = sp + O_R2;
    float* Qf   = sp + O_Q;
    float* Kf   = sp + O_K;
    float* wQKf = sp + O_WQKF;
    float* SCo  = sp + O_SC;

    bf16* hbH = (bf16*)(sp + O_BHB); bf16* hbL = (bf16*)(sp + O_BHL);
    bf16* xvH = (bf16*)(sp + O_XVH); bf16* xvL = (bf16*)(sp + O_XVL);
    bf16* xrH = (bf16*)(sp + O_XRH); bf16* xrL = (bf16*)(sp + O_XRL);
    bf16* atH = (bf16*)(sp + O_ATH); bf16* atL = (bf16*)(sp + O_ATL);
    bf16* rkH = (bf16*)(sp + O_RKH); bf16* rkL = (bf16*)(sp + O_RKL);
    bf16* KcH = (bf16*)(sp + O_KCH); bf16* KcL = (bf16*)(sp + O_KCL);

    bf16* wTMVh = (bf16*)(sp + O_WTMV); bf16* wTMVl = wTMVh + 1048576L;
    bf16* wTMRh = (bf16*)(sp + O_WTMR); bf16* wTMRl = wTMRh + 1048576L;
    bf16* wSAVh = (bf16*)(sp + O_WSAV); bf16* wSAVl = wSAVh + 1048576L;
    bf16* wSAOh = (bf16*)(sp + O_WSAO); bf16* wSAOl = wSAOh + 1048576L;
    bf16* wTMOh = (bf16*)(sp + O_WTMO); bf16* wTMOl = wTMOh + 1048576L;
    bf16* wCMRh = (bf16*)(sp + O_WCMR); bf16* wCMRl = wCMRh + 1048576L;
    bf16* wCMKh = (bf16*)(sp + O_WCMK); bf16* wCMKl = wCMKh + 4194304L;
    bf16* wCMVh = (bf16*)(sp + O_WCMV); bf16* wCMVl = wCMVh + 4194304L;

    // fused weight splits
    {
        SplitJobs6 s6;
        s6.j[0] = {tm_value_w,  wTMVh, wTMVl};
        s6.j[1] = {tm_recept_w, wTMRh, wTMRl};
        s6.j[2] = {sa_v_w,      wSAVh, wSAVl};
        s6.j[3] = {sa_o_w,      wSAOh, wSAOl};
        s6.j[4] = {tm_out_w,    wTMOh, wTMOl};
        s6.j[5] = {cm_recept_w, wCMRh, wCMRl};
        split6<<<dim3(2048, 6, 1), 256>>>(s6, 1048576L);
        SplitJobs2 s2;
        s2.j[0] = {cm_key_w,   wCMKh, wCMKl};
        s2.j[1] = {cm_value_w, wCMVh, wCMVl};
        split2<<<dim3(8192, 2, 1), 256>>>(s2, 4194304L);
        concat_qk<<<512, 256>>>(sa_q_w, sa_k_w, wQKf);
    }

    // --- time-mix branch ---
    rmsnorm_kernel<1><<<NROWS, 256>>>(x, norm1_w, hF, hbH, hbL);
    mix2_kernel<<<NROWS, 256>>>(hF, tm_mix_v, tm_mix_r, xvH, xvL, xrH, xrL);

    launch_bf(0, xvH, xvL, wTMVh, wTMVl, nullptr, nullptr, nullptr,
              Vtm, nullptr, nullptr, NROWS, D_DIM, D_DIM);
    launch_bf(0, xrH, xrL, wTMRh, wTMRl, nullptr, nullptr, nullptr,
              Rtm, nullptr, nullptr, NROWS, D_DIM, D_DIM);

    // Q||K projection on tf32x3 precision path
    {
        dim3 g(1, NROWS / 128, 1);
        gemm_tf<2><<<g, 256, TF_DSMEM>>>(hF, wQKf, sa_q_b, sa_k_b,
                                         nullptr, Qf, Kf, NROWS, 128, D_DIM,
                                         1.f, 0, 0, 0);
    }

    launch_bf(0, hbH, hbL, wSAVh, wSAVl, sa_v_b, nullptr, nullptr,
              Vv, nullptr, nullptr, NROWS, D_DIM, D_DIM);

    // scores[b] = (Q[b] @ K[b]^T) / 8 on tf32x3
    {
        dim3 g(S_LEN / 128, S_LEN / 128, B_SZ);
        gemm_tf<0><<<g, 256, TF_DSMEM>>>(Qf, Kf, nullptr, nullptr,
                                         SCo, nullptr, nullptr, S_LEN, S_LEN, A_DIM,
                                         0.125f, (long)S_LEN * A_DIM,
                                         (long)S_LEN * A_DIM, (long)S_LEN * S_LEN);
    }

    sparse_attn_kernel<<<NROWS, 256>>>(SCo, Vv, atH, atL);

    // rkv = sigmoid(Rtm) * (attn@W_o + b_o + Vtm) -> bf16 pair
    launch_bf(3, atH, atL, wSAOh, wSAOl, sa_o_b, Rtm, Vtm,
              nullptr, rkH, rkL, NROWS, D_DIM, D_DIM);

    // x2 = x + rkv @ W_out
    launch_bf(4, rkH, rkL, wTMOh, wTMOl, nullptr, x, nullptr,
              x2, nullptr, nullptr, NROWS, D_DIM, D_DIM);

    // --- channel-mix branch ---
    rmsnorm_kernel<0><<<NROWS, 256>>>(x2, norm2_w, hF, nullptr, nullptr);
    mix2_kernel<<<NROWS, 256>>>(hF, cm_mix_k, cm_mix_r, xvH, xvL, xrH, xrL);

    // Kc = relu(xk2 @ W_k)^2 -> bf16 pair
    launch_bf(1, xvH, xvL, wCMKh, wCMKl, nullptr, nullptr, nullptr,
              nullptr, KcH, KcL, NROWS, DI_DIM, D_DIM);
    launch_bf(0, xrH, xrL, wCMRh, wCMRl, nullptr, nullptr, nullptr,
              R2, nullptr, nullptr, NROWS, D_DIM, D_DIM);

    // out = x2 + sigmoid(R2) * (Kc @ W_v)
    launch_bf(5, KcH, KcL, wCMVh, wCMVl, nullptr, x2, R2,
              out, nullptr, nullptr, NROWS, D_DIM, DI_DIM);
}

// round 12
// speedup vs baseline: 2.1992x; 1.0225x over previous
#include <cuda_runtime.h>
#include <cuda_bf16.h>
#include <math.h>
#include <stdint.h>

// Problem constants
#define D_DIM   1024
#define S_LEN   4096
#define B_SZ    2
#define A_DIM   64
#define DI_DIM  4096
#define TOPK    32
#define NROWS   (B_SZ * S_LEN)                 // 8192
#define ROWELEMS ((long)NROWS * D_DIM)         // 8,388,608

#define NEG_INF (-3.402823466e38f)

// ---------------------------------------------------------------------------
// Scratch layout (float offsets; bf16 arrays overlay pairs of floats)
// ---------------------------------------------------------------------------
static const long O_HF   = 0L;
static const long O_VTM  = 8388608L;
static const long O_RTM  = 16777216L;
static const long O_VV   = 25165824L;
static const long O_X2   = 33554432L;
static const long O_R2   = 41943040L;
static const long O_Q    = 50331648L;   // 524288 fp32
static const long O_K    = 50855936L;   // 524288 fp32
static const long O_WQKF = 51380224L;   // 131072 fp32 (concat q/k weights)
static const long O_SC   = 51511296L;   // 33554432 fp32
// bf16 arrays (float-offset; each float slot holds 2 bf16)
static const long O_BHB = 85065728L;
static const long O_BHL = 89260032L;
static const long O_XVH = 93454336L;
static const long O_XVL = 97648640L;
static const long O_XRH = 101842944L;
static const long O_XRL = 106037248L;
static const long O_ATH = 110231552L;
static const long O_ATL = 114425856L;
static const long O_RKH = 118620160L;
static const long O_RKL = 122814464L;
static const long O_KCH = 127008768L;
static const long O_KCL = 143785984L;
static const long O_WB  = 160563200L;
static const long O_WTMV = O_WB;
static const long O_WTMR = O_WTMV + 1048576L;
static const long O_WSAV = O_WTMR + 1048576L;
static const long O_WSAO = O_WSAV + 1048576L;
static const long O_WTMO = O_WSAO + 1048576L;
static const long O_WCMR = O_WTMO + 1048576L;
static const long O_WCMK = O_WCMR + 1048576L;
static const long O_WCMV = O_WCMK + 4194304L;
// end = O_WCMV + 4194304 = 175243264

__device__ __align__(16) float g_scratch[175243264];

// ===========================================================================
// helpers
// ===========================================================================
__device__ __forceinline__ uint32_t smem_u32(const void* p) {
    uint32_t a;
    asm("{ .reg .u64 t; cvta.to.shared.u64 t, %1; cvt.u32.u64 %0, t; }"
        : "=r"(a) : "l"(p));
    return a;
}
__device__ __forceinline__ uint32_t f2tf32(float x) {
    uint32_t r;
    asm("cvt.rna.tf32.f32 %0, %1;" : "=r"(r) : "f"(x));
    return r;
}
__device__ __forceinline__ void split_tf32(uint32_t xbits, uint32_t& hi, uint32_t& lo) {
    float x = __uint_as_float(xbits);
    hi = f2tf32(x);
    lo = f2tf32(x - __uint_as_float(hi));
}
__device__ __forceinline__ float sigmoidf_(float x) { return 1.f / (1.f + expf(-x)); }

__device__ __forceinline__ void cp16(uint32_t s, const void* g) {
    asm volatile("cp.async.cg.shared.global [%0], [%1], 16;" :: "r"(s), "l"(g));
}

// scalar bf16 hi/lo split store
__device__ __forceinline__ void bsplit_store(__nv_bfloat16* H, __nv_bfloat16* L,
                                             long i, float v) {
    __nv_bfloat16 h = __float2bfloat16(v);
    H[i] = h;
    L[i] = __float2bfloat16(v - __bfloat162float(h));
}
__device__ __forceinline__ void bpair_store(__nv_bfloat16* H, __nv_bfloat16* L,
                                            long idx, float vx, float vy) {
    __nv_bfloat16 hx = __float2bfloat16(vx);
    __nv_bfloat16 hy = __float2bfloat16(vy);
    __nv_bfloat16 lx = __float2bfloat16(vx - __bfloat162float(hx));
    __nv_bfloat16 ly = __float2bfloat16(vy - __bfloat162float(hy));
    __nv_bfloat162 hp; hp.x = hx; hp.y = hy;
    __nv_bfloat162 lp; lp.x = lx; lp.y = ly;
    *(__nv_bfloat162*)(H + idx) = hp;
    *(__nv_bfloat162*)(L + idx) = lp;
}

__device__ __forceinline__ void mma1688(float* c, const uint32_t* a, const uint32_t* b) {
    asm volatile(
        "mma.sync.aligned.m16n8k8.row.col.f32.tf32.tf32.f32 "
        "{%0,%1,%2,%3}, {%4,%5,%6,%7}, {%8,%9}, {%0,%1,%2,%3};"
        : "+f"(c[0]), "+f"(c[1]), "+f"(c[2]), "+f"(c[3])
        : "r"(a[0]), "r"(a[1]), "r"(a[2]), "r"(a[3]), "r"(b[0]), "r"(b[1]));
}
__device__ __forceinline__ void mma16816(float* c, const uint32_t* a, const uint32_t* b) {
    asm volatile(
        "mma.sync.aligned.m16n8k16.row.col.f32.bf16.bf16.f32 "
        "{%0,%1,%2,%3}, {%4,%5,%6,%7}, {%8,%9}, {%0,%1,%2,%3};"
        : "+f"(c[0]), "+f"(c[1]), "+f"(c[2]), "+f"(c[3])
        : "r"(a[0]), "r"(a[1]), "r"(a[2]), "r"(a[3]), "r"(b[0]), "r"(b[1]));
}
__device__ __forceinline__ void ldm_x4(uint32_t* r, uint32_t a) {
    asm volatile("ldmatrix.sync.aligned.m8n8.x4.shared.b16 {%0,%1,%2,%3}, [%4];"
        : "=r"(r[0]), "=r"(r[1]), "=r"(r[2]), "=r"(r[3]) : "r"(a));
}

// ===========================================================================
// bf16x3 GEMM (NT): C = (Ah+Al)(Bh+Bl)^T via al*bh + ah*bl + ah*bh
// BM=BN=128, BK=32 bf16, 3-stage cp.async, single-sync pipeline, 256 thr,
// warp 2m x 4n, 64x32 warp tile; fragments via hoisted ldmatrix.x4.
// Optional DUAL second GEMM selected by blockIdx.z (MODE 0 only).
// MODEs: 0: Of = acc (+bias1)     1: relu(acc)^2 -> (Oh,Ol)
//        3: sigmoid(ex1)*(acc+bias1+ex2) -> (Oh,Ol)
//        4: Of = ex1 + acc        5: Of = ex1 + sigmoid(ex2)*acc
// ===========================================================================
#define BTILE 8192                    // 128*32*2
#define BSTG  (4 * BTILE)             // 32768
#define BNSTG 3
#define BF_DSMEM (BNSTG * BSTG + 128) // 98432

__device__ __forceinline__ void load_stage_bf(
    uint32_t sbase, int stage,
    const __nv_bfloat16* __restrict__ Ah, const __nv_bfloat16* __restrict__ Al,
    const __nv_bfloat16* __restrict__ Bh, const __nv_bfloat16* __restrict__ Bl,
    int bm, int bn, int k0, int K, int tid)
{
    uint32_t s = sbase + stage * BSTG;
#pragma unroll
    for (int j = 0; j < 2; j++) {
        int gi = tid + j * 256;        // 0..511
        int row = gi >> 2, g = gi & 3;
        uint32_t so = (uint32_t)(row * 64 + ((g ^ ((row >> 1) & 3)) << 4));
        long ao = (long)(bm + row) * K + k0 + g * 8;
        long bo = (long)(bn + row) * K + k0 + g * 8;
        cp16(s + so,             Ah + ao);
        cp16(s + BTILE + so,     Al + ao);
        cp16(s + 2 * BTILE + so, Bh + bo);
        cp16(s + 3 * BTILE + so, Bl + bo);
    }
}

template<int MODE>
__global__ void __launch_bounds__(256, 2) gemm_bf(
    const __nv_bfloat16* __restrict__ Ah, const __nv_bfloat16* __restrict__ Al,
    const __nv_bfloat16* __restrict__ Bh, const __nv_bfloat16* __restrict__ Bl,
    const float* __restrict__ bias1,
    const float* __restrict__ ex1, const float* __restrict__ ex2,
    float* __restrict__ Of,
    __nv_bfloat16* __restrict__ Oh, __nv_bfloat16* __restrict__ Ol,
    int M, int N, int K,
    const __nv_bfloat16* A2h, const __nv_bfloat16* A2l,
    const __nv_bfloat16* B2h, const __nv_bfloat16* B2l, float* Of2)
{
    extern __shared__ __align__(16) char dsm[];

    if (MODE == 0 && blockIdx.z == 1) {
        Ah = A2h; Al = A2l; Bh = B2h; Bl = B2l; Of = Of2;
    }

    const int tid  = threadIdx.x;
    const int wid  = tid >> 5;
    const int lane = tid & 31;
    const int wm   = wid & 1;
    const int wn   = wid >> 1;
    const int bm = blockIdx.y * 128;
    const int bn = blockIdx.x * 128;
    const int KT = K / 32;
    const int lr = lane >> 2, lk = lane & 3;

    float acc[4][4][4];
#pragma unroll
    for (int i = 0; i < 4; i++)
#pragma unroll
        for (int j = 0; j < 4; j++)
#pragma unroll
            for (int r = 0; r < 4; r++) acc[i][j][r] = 0.f;

    // ldmatrix per-lane swizzled base offsets (granule bit from lane>>4)
    uint32_t offA[4], offB[2];
    {
        int ga = (lane >> 4) & 1;
        int rb = wm * 64 + (lane & 15);
#pragma unroll
        for (int mf = 0; mf < 4; mf++) {
            int row = rb + mf * 16;
            offA[mf] = (uint32_t)(row * 64 + ((ga ^ ((row >> 1) & 3)) << 4));
        }
#pragma unroll
        for (int pg = 0; pg < 2; pg++) {
            int row = wn * 32 + pg * 16 + (lane & 15);
            offB[pg] = (uint32_t)(row * 64 + ((ga ^ ((row >> 1) & 3)) << 4)) + 2 * BTILE;
        }
    }

    uint32_t sbase = (smem_u32(dsm) + 127u) & ~127u;
    load_stage_bf(sbase, 0, Ah, Al, Bh, Bl, bm, bn, 0, K, tid);
    asm volatile("cp.async.commit_group;" ::: "memory");
    load_stage_bf(sbase, 1, Ah, Al, Bh, Bl, bm, bn, 32, K, tid);
    asm volatile("cp.async.commit_group;" ::: "memory");

    int stage = 0;
    for (int kt = 0; kt < KT; kt++) {
        // stage kt%3 ready when all but the newest group have landed
        asm volatile("cp.async.wait_group 1;" ::: "memory");
        __syncthreads();   // also orders kt-1 MMAs before overwriting stage kt+2

        int ps = kt + 2;
        if (ps < KT) {
            int pstage = stage + 2; if (pstage >= BNSTG) pstage -= BNSTG;
            load_stage_bf(sbase, pstage, Ah, Al, Bh, Bl, bm, bn, ps * 32, K, tid);
        }
        asm volatile("cp.async.commit_group;" ::: "memory");

        uint32_t st = sbase + stage * BSTG;

#pragma unroll
        for (int ks = 0; ks < 2; ks++) {
            uint32_t kx = (uint32_t)(ks << 5);
            // hoist ALL fragment loads (B first: they feed the first MMAs)
            uint32_t tb0[4], tl0[4], tb1[4], tl1[4];
            ldm_x4(tb0, (st + offB[0]) ^ kx);
            ldm_x4(tl0, (st + offB[0] + BTILE) ^ kx);
            ldm_x4(tb1, (st + offB[1]) ^ kx);
            ldm_x4(tl1, (st + offB[1] + BTILE) ^ kx);
            uint32_t ah[4][4], al[4][4];
#pragma unroll
            for (int mf = 0; mf < 4; mf++) {
                ldm_x4(ah[mf], (st + offA[mf]) ^ kx);
                ldm_x4(al[mf], (st + offA[mf] + BTILE) ^ kx);
            }
            uint32_t b_h[4][2] = {{tb0[0],tb0[2]},{tb0[1],tb0[3]},
                                  {tb1[0],tb1[2]},{tb1[1],tb1[3]}};
            uint32_t b_l[4][2] = {{tl0[0],tl0[2]},{tl0[1],tl0[3]},
                                  {tl1[0],tl1[2]},{tl1[1],tl1[3]}};
#pragma unroll
            for (int mf = 0; mf < 4; mf++)
#pragma unroll
                for (int nf = 0; nf < 4; nf++) {
                    mma16816(acc[mf][nf], al[mf], b_h[nf]);
                    mma16816(acc[mf][nf], ah[mf], b_l[nf]);
                    mma16816(acc[mf][nf], ah[mf], b_h[nf]);
                }
        }
        stage++; if (stage >= BNSTG) stage = 0;
    }

    // epilogue
#pragma unroll
    for (int mf = 0; mf < 4; mf++) {
        int r0 = bm + wm * 64 + mf * 16 + lr;
#pragma unroll
        for (int nf = 0; nf < 4; nf++) {
            int c0 = bn + wn * 32 + nf * 8 + lk * 2;
#pragma unroll
            for (int h = 0; h < 2; h++) {
                int row = r0 + h * 8;
                long idx = (long)row * N + c0;
                float vx = acc[mf][nf][2 * h + 0];
                float vy = acc[mf][nf][2 * h + 1];
                if (MODE == 0) {
                    if (bias1) { vx += bias1[c0]; vy += bias1[c0 + 1]; }
                    *(float2*)(Of + idx) = make_float2(vx, vy);
                } else if (MODE == 1) {
                    vx = fmaxf(vx, 0.f); vx *= vx;
                    vy = fmaxf(vy, 0.f); vy *= vy;
                    bpair_store(Oh, Ol, idx, vx, vy);
                } else if (MODE == 3) {
                    vx += bias1[c0]; vy += bias1[c0 + 1];
                    float rx = sigmoidf_(ex1[idx])     * (vx + ex2[idx]);
                    float ry = sigmoidf_(ex1[idx + 1]) * (vy + ex2[idx + 1]);
                    bpair_store(Oh, Ol, idx, rx, ry);
                } else if (MODE == 4) {
                    *(float2*)(Of + idx) = make_float2(ex1[idx] + vx, ex1[idx + 1] + vy);
                } else { // 5
                    float rx = ex1[idx]     + sigmoidf_(ex2[idx])     * vx;
                    float ry = ex1[idx + 1] + sigmoidf_(ex2[idx + 1]) * vy;
                    *(float2*)(Of + idx) = make_float2(rx, ry);
                }
            }
        }
    }
}

// ===========================================================================
// tf32x3 GEMM (NT) with in-kernel split (fp32 inputs) — precision path.
// MODEs: 0: O1 = alpha*acc (batched via blockIdx.z strides)
//        2: QK: col<64 -> Qf=acc+qb, col>=64 -> Kf=acc+kb (fp32 [row][64])
// ===========================================================================
#define TBKF 16
#define T_A_BYTES (128 * TBKF * 4)      // 8192
#define T_STG     (2 * T_A_BYTES)       // 16384
#define TNSTG 4
#define TF_DSMEM (TNSTG * T_STG)        // 65536

__device__ __forceinline__ uint32_t lde(const uint32_t* t, int row, int k) {
    int g = k >> 2;
    return t[row * 16 + (((g ^ ((row >> 1) & 3)) << 2) | (k & 3))];
}

__device__ __forceinline__ void load_stage_tf(
    uint32_t sbase, int stage, const float* __restrict__ A,
    const float* __restrict__ B, int bm, int bn, int k0, int K, int tid)
{
    uint32_t sa = sbase + stage * T_STG;
    uint32_t sb = sa + T_A_BYTES;
    int row = tid >> 1;
    int g0 = (tid & 1) * 2;
#pragma unroll
    for (int j = 0; j < 2; j++) {
        int g = g0 + j;
        uint32_t so = (uint32_t)(row * 64 + ((g ^ ((row >> 1) & 3)) << 4));
        cp16(sa + so, A + (long)(bm + row) * K + k0 + g * 4);
        cp16(sb + so, B + (long)(bn + row) * K + k0 + g * 4);
    }
}

template<int MODE>
__global__ void __launch_bounds__(256) gemm_tf(
    const float* __restrict__ A, const float* __restrict__ B,
    const float* __restrict__ qb, const float* __restrict__ kb,
    float* __restrict__ O1, float* __restrict__ Qf, float* __restrict__ Kf,
    int M, int N, int K, float alpha, long sA, long sB, long sC)
{
    extern __shared__ __align__(16) char dsm[];

    A += (long)blockIdx.z * sA;
    B += (long)blockIdx.z * sB;
    O1 += (long)blockIdx.z * sC;

    const int tid  = threadIdx.x;
    const int wid  = tid >> 5;
    const int lane = tid & 31;
    const int wm   = wid & 1;
    const int wn   = wid >> 1;
    const int bm = blockIdx.y * 128;
    const int bn = blockIdx.x * 128;
    const int KT = K / TBKF;

    uint32_t sbase = smem_u32(dsm);

    float acc[4][4][4];
#pragma unroll
    for (int i = 0; i < 4; i++)
#pragma unroll
        for (int j = 0; j < 4; j++)
#pragma unroll
            for (int r = 0; r < 4; r++) acc[i][j][r] = 0.f;

#pragma unroll
    for (int s = 0; s < TNSTG - 1; s++) {
        if (s < KT) load_stage_tf(sbase, s, A, B, bm, bn, s * TBKF, K, tid);
        asm volatile("cp.async.commit_group;" ::: "memory");
    }

    const int lr = lane >> 2;
    const int lk = lane & 3;

    for (int kt = 0; kt < KT; kt++) {
        __syncthreads();
        if (kt + 3 < KT)
            load_stage_tf(sbase, (kt + 3) & 3, A, B, bm, bn, (kt + 3) * TBKF, K, tid);
        asm volatile("cp.async.commit_group;" ::: "memory");
        asm volatile("cp.async.wait_group 3;" ::: "memory");
        __syncthreads();

        const uint32_t* sa = (const uint32_t*)(dsm + (size_t)(kt & 3) * T_STG);
        const uint32_t* sb = sa + 128 * TBKF;

#pragma unroll
        for (int ks = 0; ks < 2; ks++) {
            int kbase = ks * 8;
            uint32_t ah[4][4], al[4][4], bh[4][2], bl[4][2];
#pragma unroll
            for (int mf = 0; mf < 4; mf++) {
                int r0 = wm * 64 + mf * 16 + lr;
                split_tf32(lde(sa, r0,     kbase + lk),     ah[mf][0], al[mf][0]);
                split_tf32(lde(sa, r0 + 8, kbase + lk),     ah[mf][1], al[mf][1]);
                split_tf32(lde(sa, r0,     kbase + lk + 4), ah[mf][2], al[mf][2]);
                split_tf32(lde(sa, r0 + 8, kbase + lk + 4), ah[mf][3], al[mf][3]);
            }
#pragma unroll
            for (int nf = 0; nf < 4; nf++) {
                int n0 = wn * 32 + nf * 8 + lr;
                split_tf32(lde(sb, n0, kbase + lk),     bh[nf][0], bl[nf][0]);
                split_tf32(lde(sb, n0, kbase + lk + 4), bh[nf][1], bl[nf][1]);
            }
#pragma unroll
            for (int mf = 0; mf < 4; mf++)
#pragma unroll
                for (int nf = 0; nf < 4; nf++) {
                    mma1688(acc[mf][nf], al[mf], bh[nf]);
                    mma1688(acc[mf][nf], ah[mf], bl[nf]);
                    mma1688(acc[mf][nf], ah[mf], bh[nf]);
                }
        }
    }

#pragma unroll
    for (int mf = 0; mf < 4; mf++) {
        int r0 = bm + wm * 64 + mf * 16 + lr;
#pragma unroll
        for (int nf = 0; nf < 4; nf++) {
            int c0 = bn + wn * 32 + nf * 8 + lk * 2;
#pragma unroll
            for (int h = 0; h < 2; h++) {
                int row = r0 + h * 8;
                float vx = acc[mf][nf][2 * h + 0] * alpha;
                float vy = acc[mf][nf][2 * h + 1] * alpha;
                if (MODE == 0) {
                    *(float2*)(O1 + (long)row * N + c0) = make_float2(vx, vy);
                } else { // MODE 2: Q||K
                    if (c0 < 64) {
                        vx += qb[c0]; vy += qb[c0 + 1];
                        *(float2*)(Qf + (long)row * 64 + c0) = make_float2(vx, vy);
                    } else {
                        vx += kb[c0 - 64]; vy += kb[c0 - 63];
                        *(float2*)(Kf + (long)row * 64 + c0 - 64) = make_float2(vx, vy);
                    }
                }
            }
        }
    }
}

// ---------------------------------------------------------------------------
// Weight splits: fp32 -> bf16 hi/lo (fused batches)
// ---------------------------------------------------------------------------
struct SplitJob { const float* src; __nv_bfloat16* h; __nv_bfloat16* l; };
struct SplitJobs6 { SplitJob j[6]; };
struct SplitJobs2 { SplitJob j[2]; };

__global__ void __launch_bounds__(256) split6(SplitJobs6 jobs, long n)
{
    const SplitJob jb = jobs.j[blockIdx.y];
    long i = ((long)blockIdx.x * 256 + threadIdx.x) * 2;
    if (i < n) bpair_store(jb.h, jb.l, i, jb.src[i], jb.src[i + 1]);
}
__global__ void __launch_bounds__(256) split2(SplitJobs2 jobs, long n)
{
    const SplitJob jb = jobs.j[blockIdx.y];
    long i = ((long)blockIdx.x * 256 + threadIdx.x) * 2;
    if (i < n) bpair_store(jb.h, jb.l, i, jb.src[i], jb.src[i + 1]);
}

__global__ void __launch_bounds__(256) concat_qk(
    const float* __restrict__ q, const float* __restrict__ k, float* __restrict__ o)
{
    int i = blockIdx.x * 256 + threadIdx.x;   // n = 131072
    o[i] = (i < 65536) ? q[i] : k[i - 65536];
}

// ---------------------------------------------------------------------------
// Fused RMSNorm + token-shift mixing. One block per row; computes the norm
// of row AND prev row (expression-identical to the two-kernel version),
// then emits both mixes as bf16 hi/lo pairs. Optionally writes normalized
// row as fp32 (hF) + bf16 pair (hbH/hbL) for the attention branch.
// ---------------------------------------------------------------------------
template<int WRITE_H>
__global__ void __launch_bounds__(256) norm_mix_kernel(
    const float* __restrict__ x, const float* __restrict__ w,
    const float* __restrict__ mA, const float* __restrict__ mB,
    __nv_bfloat16* __restrict__ oAh, __nv_bfloat16* __restrict__ oAl,
    __nv_bfloat16* __restrict__ oBh, __nv_bfloat16* __restrict__ oBl,
    float* __restrict__ hF, __nv_bfloat16* __restrict__ hbH,
    __nv_bfloat16* __restrict__ hbL)
{
    long row = blockIdx.x;
    long prev = ((row & (S_LEN - 1)) == 0) ? row : row - 1;
    int tid = threadIdx.x;
    const float* xc = x + row * D_DIM;
    const float* xp = x + prev * D_DIM;

    float c[4], p[4];
    float sc_ = 0.f, sp_ = 0.f;
#pragma unroll
    for (int d = 0; d < 4; d++) {
        c[d] = xc[tid + d * 256];
        p[d] = xp[tid + d * 256];
        sc_ += c[d] * c[d];
        sp_ += p[d] * p[d];
    }
#pragma unroll
    for (int o = 16; o > 0; o >>= 1) {
        sc_ += __shfl_xor_sync(0xffffffffu, sc_, o);
        sp_ += __shfl_xor_sync(0xffffffffu, sp_, o);
    }

    __shared__ float redc[8], redp[8];
    __shared__ float s_invc, s_invp;
    if ((tid & 31) == 0) { redc[tid >> 5] = sc_; redp[tid >> 5] = sp_; }
    __syncthreads();
    if (tid == 0) {
        float tc = 0.f, tp = 0.f;
#pragma unroll
        for (int i = 0; i < 8; i++) { tc += redc[i]; tp += redp[i]; }
        s_invc = 1.0f / (sqrtf(tc / (float)D_DIM) + 1e-8f);
        s_invp = 1.0f / (sqrtf(tp / (float)D_DIM) + 1e-8f);
    }
    __syncthreads();
    float invc = s_invc, invp = s_invp;

#pragma unroll
    for (int d = 0; d < 4; d++) {
        int cc = tid + d * 256;
        long ci = row * D_DIM + cc;
        float nc = w[cc] * c[d] * invc;
        float np = w[cc] * p[d] * invp;
        float a = mA[cc], b = mB[cc];
        bsplit_store(oAh, oAl, ci, nc * a + np * (1.f - a));
        bsplit_store(oBh, oBl, ci, nc * b + np * (1.f - b));
        if (WRITE_H) {
            hF[ci] = nc;
            bsplit_store(hbH, hbL, ci, nc);
        }
    }
}

// ---------------------------------------------------------------------------
// Sparse attention: chunked top-32, softmax, attn@V -> bf16 pair out.
// ---------------------------------------------------------------------------
__global__ void __launch_bounds__(256) sparse_attn_kernel(
    const float* __restrict__ scores, const float* __restrict__ V,
    __nv_bfloat16* __restrict__ oh, __nv_bfloat16* __restrict__ ol)
{
    __shared__ float sc[S_LEN];
    __shared__ float cmax[128];
    __shared__ float selV[TOPK];
    __shared__ int   selI[TOPK];
    __shared__ float wsel[TOPK];

    long row = blockIdx.x;
    long b = row >> 12;
    int tid = threadIdx.x;
    int lane = tid & 31;

    const float* srow = scores + row * S_LEN;
    for (int i = tid; i < S_LEN; i += 256) sc[i] = srow[i];
    __syncthreads();

    if (tid < 128) {
        float m = NEG_INF;
#pragma unroll 8
        for (int i = 0; i < 32; i++) m = fmaxf(m, sc[tid * 32 + i]);
        cmax[tid] = m;
    }
    __syncthreads();

    if (tid < 32) {
        for (int it = 0; it < TOPK; it++) {
            float bv = NEG_INF; int bc = 0;
#pragma unroll
            for (int j = 0; j < 4; j++) {
                int c = lane * 4 + j;
                float v = cmax[c];
                if (v > bv) { bv = v; bc = c; }
            }
#pragma unroll
            for (int o = 16; o > 0; o >>= 1) {
                float ov = __shfl_down_sync(0xffffffffu, bv, o);
                int   oc = __shfl_down_sync(0xffffffffu, bc, o);
                if (ov > bv || (ov == bv && oc < bc)) { bv = ov; bc = oc; }
            }
            bc = __shfl_sync(0xffffffffu, bc, 0);

            float v = sc[bc * 32 + lane];
            float mv = v; int mi = lane;
#pragma unroll
            for (int o = 16; o > 0; o >>= 1) {
                float ov = __shfl_down_sync(0xffffffffu, mv, o);
                int   oi = __shfl_down_sync(0xffffffffu, mi, o);
                if (ov > mv || (ov == mv && oi < mi)) { mv = ov; mi = oi; }
            }
            mv = __shfl_sync(0xffffffffu, mv, 0);
            mi = __shfl_sync(0xffffffffu, mi, 0);

            if (lane == mi) { sc[bc * 32 + lane] = NEG_INF; v = NEG_INF; }
            if (lane == 0) { selV[it] = mv; selI[it] = bc * 32 + mi; }

            float nm = v;
#pragma unroll
            for (int o = 16; o > 0; o >>= 1)
                nm = fmaxf(nm, __shfl_down_sync(0xffffffffu, nm, o));
            if (lane == 0) cmax[bc] = nm;
        }
        float m = __shfl_sync(0xffffffffu, selV[0], 0);
        float e = expf(selV[lane] - m);
        float s = e;
#pragma unroll
        for (int o = 16; o > 0; o >>= 1) s += __shfl_xor_sync(0xffffffffu, s, o);
        wsel[lane] = e / s;
    }
    __syncthreads();

    float acc[4] = {0.f, 0.f, 0.f, 0.f};
    const float* Vb = V + b * (long)S_LEN * D_DIM;
#pragma unroll 1
    for (int j = 0; j < TOPK; j++) {
        float w = wsel[j];
        const float* vr = Vb + (long)selI[j] * D_DIM;
#pragma unroll
        for (int d = 0; d < 4; d++) acc[d] += w * vr[tid + d * 256];
    }
#pragma unroll
    for (int d = 0; d < 4; d++)
        bsplit_store(oh, ol, row * D_DIM + tid + d * 256, acc[d]);
}

// ---------------------------------------------------------------------------
// Host launchers
// ---------------------------------------------------------------------------
typedef __nv_bfloat16 bf16;

static void launch_bf(int mode,
    const bf16* Ah, const bf16* Al, const bf16* Bh, const bf16* Bl,
    const float* b1, const float* e1, const float* e2,
    float* Of, bf16* Oh, bf16* Ol, int M, int N, int K,
    const bf16* A2h = nullptr, const bf16* A2l = nullptr,
    const bf16* B2h = nullptr, const bf16* B2l = nullptr,
    float* Of2 = nullptr, int gz = 1)
{
    dim3 grid(N / 128, M / 128, gz);
    switch (mode) {
    case 0: gemm_bf<0><<<grid, 256, BF_DSMEM>>>(Ah,Al,Bh,Bl,b1,e1,e2,Of,Oh,Ol,M,N,K,A2h,A2l,B2h,B2l,Of2); break;
    case 1: gemm_bf<1><<<grid, 256, BF_DSMEM>>>(Ah,Al,Bh,Bl,b1,e1,e2,Of,Oh,Ol,M,N,K,A2h,A2l,B2h,B2l,Of2); break;
    case 3: gemm_bf<3><<<grid, 256, BF_DSMEM>>>(Ah,Al,Bh,Bl,b1,e1,e2,Of,Oh,Ol,M,N,K,A2h,A2l,B2h,B2l,Of2); break;
    case 4: gemm_bf<4><<<grid, 256, BF_DSMEM>>>(Ah,Al,Bh,Bl,b1,e1,e2,Of,Oh,Ol,M,N,K,A2h,A2l,B2h,B2l,Of2); break;
    default: gemm_bf<5><<<grid, 256, BF_DSMEM>>>(Ah,Al,Bh,Bl,b1,e1,e2,Of,Oh,Ol,M,N,K,A2h,A2l,B2h,B2l,Of2); break;
    }
}

extern "C" void kernel_launch(void* const* d_in, const int* in_sizes, int n_in,
                              void* d_out, int out_size)
{
    const float* x         = (const float*)d_in[0];
    const float* norm1_w   = (const float*)d_in[1];
    const float* tm_mix_v  = (const float*)d_in[3];
    const float* tm_mix_r  = (const float*)d_in[4];
    const float* tm_value_w  = (const float*)d_in[6];
    const float* tm_recept_w = (const float*)d_in[7];
    const float* tm_out_w    = (const float*)d_in[8];
    const float* sa_q_w    = (const float*)d_in[9];
    const float* sa_q_b    = (const float*)d_in[10];
    const float* sa_k_w    = (const float*)d_in[11];
    const float* sa_k_b    = (const float*)d_in[12];
    const float* sa_v_w    = (const float*)d_in[13];
    const float* sa_v_b    = (const float*)d_in[14];
    const float* sa_o_w    = (const float*)d_in[15];
    const float* sa_o_b    = (const float*)d_in[16];
    const float* norm2_w   = (const float*)d_in[17];
    const float* cm_mix_k  = (const float*)d_in[18];
    const float* cm_mix_r  = (const float*)d_in[19];
    const float* cm_key_w    = (const float*)d_in[20];
    const float* cm_recept_w = (const float*)d_in[21];
    const float* cm_value_w  = (const float*)d_in[22];
    float* out = (float*)d_out;

    cudaFuncSetAttribute(gemm_bf<0>, cudaFuncAttributeMaxDynamicSharedMemorySize, BF_DSMEM);
    cudaFuncSetAttribute(gemm_bf<1>, cudaFuncAttributeMaxDynamicSharedMemorySize, BF_DSMEM);
    cudaFuncSetAttribute(gemm_bf<3>, cudaFuncAttributeMaxDynamicSharedMemorySize, BF_DSMEM);
    cudaFuncSetAttribute(gemm_bf<4>, cudaFuncAttributeMaxDynamicSharedMemorySize, BF_DSMEM);
    cudaFuncSetAttribute(gemm_bf<5>, cudaFuncAttributeMaxDynamicSharedMemorySize, BF_DSMEM);
    cudaFuncSetAttribute(gemm_tf<0>, cudaFuncAttributeMaxDynamicSharedMemorySize, TF_DSMEM);
    cudaFuncSetAttribute(gemm_tf<2>, cudaFuncAttributeMaxDynamicSharedMemorySize, TF_DSMEM);

    float* sp = nullptr;
    cudaGetSymbolAddress((void**)&sp, g_scratch);

    float* hF   = sp + O_HF;
    float* Vtm  = sp + O_VTM;
    float* Rtm  = sp + O_RTM;
    float* Vv   = sp + O_VV;
    float* x2   = sp + O_X2;
    float* R2   = sp + O_R2;
    float* Qf   = sp + O_Q;
    float* Kf   = sp + O_K;
    float* wQKf = sp + O_WQKF;
    float* SCo  = sp + O_SC;

    bf16* hbH = (bf16*)(sp + O_BHB); bf16* hbL = (bf16*)(sp + O_BHL);
    bf16* xvH = (bf16*)(sp + O_XVH); bf16* xvL = (bf16*)(sp + O_XVL);
    bf16* xrH = (bf16*)(sp + O_XRH); bf16* xrL = (bf16*)(sp + O_XRL);
    bf16* atH = (bf16*)(sp + O_ATH); bf16* atL = (bf16*)(sp + O_ATL);
    bf16* rkH = (bf16*)(sp + O_RKH); bf16* rkL = (bf16*)(sp + O_RKL);
    bf16* KcH = (bf16*)(sp + O_KCH); bf16* KcL = (bf16*)(sp + O_KCL);

    bf16* wTMVh = (bf16*)(sp + O_WTMV); bf16* wTMVl = wTMVh + 1048576L;
    bf16* wTMRh = (bf16*)(sp + O_WTMR); bf16* wTMRl = wTMRh + 1048576L;
    bf16* wSAVh = (bf16*)(sp + O_WSAV); bf16* wSAVl = wSAVh + 1048576L;
    bf16* wSAOh = (bf16*)(sp + O_WSAO); bf16* wSAOl = wSAOh + 1048576L;
    bf16* wTMOh = (bf16*)(sp + O_WTMO); bf16* wTMOl = wTMOh + 1048576L;
    bf16* wCMRh = (bf16*)(sp + O_WCMR); bf16* wCMRl = wCMRh + 1048576L;
    bf16* wCMKh = (bf16*)(sp + O_WCMK); bf16* wCMKl = wCMKh + 4194304L;
    bf16* wCMVh = (bf16*)(sp + O_WCMV); bf16* wCMVl = wCMVh + 4194304L;

    // fused weight splits
    {
        SplitJobs6 s6;
        s6.j[0] = {tm_value_w,  wTMVh, wTMVl};
        s6.j[1] = {tm_recept_w, wTMRh, wTMRl};
        s6.j[2] = {sa_v_w,      wSAVh, wSAVl};
        s6.j[3] = {sa_o_w,      wSAOh, wSAOl};
        s6.j[4] = {tm_out_w,    wTMOh, wTMOl};
        s6.j[5] = {cm_recept_w, wCMRh, wCMRl};
        split6<<<dim3(2048, 6, 1), 256>>>(s6, 1048576L);
        SplitJobs2 s2;
        s2.j[0] = {cm_key_w,   wCMKh, wCMKl};
        s2.j[1] = {cm_value_w, wCMVh, wCMVl};
        split2<<<dim3(8192, 2, 1), 256>>>(s2, 4194304L);
        concat_qk<<<512, 256>>>(sa_q_w, sa_k_w, wQKf);
    }

    // --- time-mix branch ---
    norm_mix_kernel<1><<<NROWS, 256>>>(x, norm1_w, tm_mix_v, tm_mix_r,
                                       xvH, xvL, xrH, xrL, hF, hbH, hbL);

    // merged dual GEMM: z=0 -> Vtm = xv @ Wv, z=1 -> Rtm = xr @ Wr
    launch_bf(0, xvH, xvL, wTMVh, wTMVl, nullptr, nullptr, nullptr,
              Vtm, nullptr, nullptr, NROWS, D_DIM, D_DIM,
              xrH, xrL, wTMRh, wTMRl, Rtm, 2);

    // Q||K projection on tf32x3 precision path
    {
        dim3 g(1, NROWS / 128, 1);
        gemm_tf<2><<<g, 256, TF_DSMEM>>>(hF, wQKf, sa_q_b, sa_k_b,
                                         nullptr, Qf, Kf, NROWS, 128, D_DIM,
                                         1.f, 0, 0, 0);
    }

    launch_bf(0, hbH, hbL, wSAVh, wSAVl, sa_v_b, nullptr, nullptr,
              Vv, nullptr, nullptr, NROWS, D_DIM, D_DIM);

    // scores[b] = (Q[b] @ K[b]^T) / 8 on tf32x3
    {
        dim3 g(S_LEN / 128, S_LEN / 128, B_SZ);
        gemm_tf<0><<<g, 256, TF_DSMEM>>>(Qf, Kf, nullptr, nullptr,
                                         SCo, nullptr, nullptr, S_LEN, S_LEN, A_DIM,
                                         0.125f, (long)S_LEN * A_DIM,
                                         (long)S_LEN * A_DIM, (long)S_LEN * S_LEN);
    }

    sparse_attn_kernel<<<NROWS, 256>>>(SCo, Vv, atH, atL);

    // rkv = sigmoid(Rtm) * (attn@W_o + b_o + Vtm) -> bf16 pair
    launch_bf(3, atH, atL, wSAOh, wSAOl, sa_o_b, Rtm, Vtm,
              nullptr, rkH, rkL, NROWS, D_DIM, D_DIM);

    // x2 = x + rkv @ W_out
    launch_bf(4, rkH, rkL, wTMOh, wTMOl, nullptr, x, nullptr,
              x2, nullptr, nullptr, NROWS, D_DIM, D_DIM);

    // --- channel-mix branch ---
    norm_mix_kernel<0><<<NROWS, 256>>>(x2, norm2_w, cm_mix_k, cm_mix_r,
                                       xvH, xvL, xrH, xrL,
                                       nullptr, nullptr, nullptr);

    // Kc = relu(xk2 @ W_k)^2 -> bf16 pair
    launch_bf(1, xvH, xvL, wCMKh, wCMKl, nullptr, nullptr, nullptr,
              nullptr, KcH, KcL, NROWS, DI_DIM, D_DIM);
    launch_bf(0, xrH, xrL, wCMRh, wCMRl, nullptr, nullptr, nullptr,
              R2, nullptr, nullptr, NROWS, D_DIM, D_DIM);

    // out = x2 + sigmoid(R2) * (Kc @ W_v)
    launch_bf(5, KcH, KcL, wCMVh, wCMVl, nullptr, x2, R2,
              out, nullptr, nullptr, NROWS, D_DIM, DI_DIM);
}

// round 13
// speedup vs baseline: 2.2682x; 1.0314x over previous
#include <cuda_runtime.h>
#include <cuda_bf16.h>
#include <math.h>
#include <stdint.h>

// Problem constants
#define D_DIM   1024
#define S_LEN   4096
#define B_SZ    2
#define A_DIM   64
#define DI_DIM  4096
#define TOPK    32
#define NROWS   (B_SZ * S_LEN)                 // 8192
#define ROWELEMS ((long)NROWS * D_DIM)         // 8,388,608

#define NEG_INF (-3.402823466e38f)

// ---------------------------------------------------------------------------
// Scratch layout (float offsets; bf16 arrays overlay pairs of floats)
// ---------------------------------------------------------------------------
static const long O_HF   = 0L;
static const long O_VTM  = 8388608L;
static const long O_RTM  = 16777216L;
static const long O_VV   = 25165824L;
static const long O_X2   = 33554432L;
static const long O_R2   = 41943040L;
static const long O_Q    = 50331648L;   // 524288 fp32
static const long O_K    = 50855936L;   // 524288 fp32
static const long O_WQKF = 51380224L;   // 131072 fp32 (concat q/k weights)
static const long O_SC   = 51511296L;   // 33554432 fp32
// bf16 arrays (float-offset; each float slot holds 2 bf16)
static const long O_BHB = 85065728L;
static const long O_BHL = 89260032L;
static const long O_XVH = 93454336L;
static const long O_XVL = 97648640L;
static const long O_XRH = 101842944L;
static const long O_XRL = 106037248L;
static const long O_ATH = 110231552L;
static const long O_ATL = 114425856L;
static const long O_RKH = 118620160L;
static const long O_RKL = 122814464L;
static const long O_KCH = 127008768L;
static const long O_KCL = 143785984L;
static const long O_WB  = 160563200L;
static const long O_WTMV = O_WB;
static const long O_WTMR = O_WTMV + 1048576L;
static const long O_WSAV = O_WTMR + 1048576L;
static const long O_WSAO = O_WSAV + 1048576L;
static const long O_WTMO = O_WSAO + 1048576L;
static const long O_WCMR = O_WTMO + 1048576L;
static const long O_WCMK = O_WCMR + 1048576L;
static const long O_WCMV = O_WCMK + 4194304L;
// end = O_WCMV + 4194304 = 175243264

__device__ __align__(16) float g_scratch[175243264];

// ===========================================================================
// helpers
// ===========================================================================
__device__ __forceinline__ uint32_t smem_u32(const void* p) {
    uint32_t a;
    asm("{ .reg .u64 t; cvta.to.shared.u64 t, %1; cvt.u32.u64 %0, t; }"
        : "=r"(a) : "l"(p));
    return a;
}
__device__ __forceinline__ uint32_t f2tf32(float x) {
    uint32_t r;
    asm("cvt.rna.tf32.f32 %0, %1;" : "=r"(r) : "f"(x));
    return r;
}
__device__ __forceinline__ void split_tf32(uint32_t xbits, uint32_t& hi, uint32_t& lo) {
    float x = __uint_as_float(xbits);
    hi = f2tf32(x);
    lo = f2tf32(x - __uint_as_float(hi));
}
__device__ __forceinline__ float sigmoidf_(float x) { return 1.f / (1.f + expf(-x)); }

__device__ __forceinline__ void cp16(uint32_t s, const void* g) {
    asm volatile("cp.async.cg.shared.global [%0], [%1], 16;" :: "r"(s), "l"(g));
}

// scalar bf16 hi/lo split store
__device__ __forceinline__ void bsplit_store(__nv_bfloat16* H, __nv_bfloat16* L,
                                             long i, float v) {
    __nv_bfloat16 h = __float2bfloat16(v);
    H[i] = h;
    L[i] = __float2bfloat16(v - __bfloat162float(h));
}
__device__ __forceinline__ void bpair_store(__nv_bfloat16* H, __nv_bfloat16* L,
                                            long idx, float vx, float vy) {
    __nv_bfloat16 hx = __float2bfloat16(vx);
    __nv_bfloat16 hy = __float2bfloat16(vy);
    __nv_bfloat16 lx = __float2bfloat16(vx - __bfloat162float(hx));
    __nv_bfloat16 ly = __float2bfloat16(vy - __bfloat162float(hy));
    __nv_bfloat162 hp; hp.x = hx; hp.y = hy;
    __nv_bfloat162 lp; lp.x = lx; lp.y = ly;
    *(__nv_bfloat162*)(H + idx) = hp;
    *(__nv_bfloat162*)(L + idx) = lp;
}

__device__ __forceinline__ void mma1688(float* c, const uint32_t* a, const uint32_t* b) {
    asm volatile(
        "mma.sync.aligned.m16n8k8.row.col.f32.tf32.tf32.f32 "
        "{%0,%1,%2,%3}, {%4,%5,%6,%7}, {%8,%9}, {%0,%1,%2,%3};"
        : "+f"(c[0]), "+f"(c[1]), "+f"(c[2]), "+f"(c[3])
        : "r"(a[0]), "r"(a[1]), "r"(a[2]), "r"(a[3]), "r"(b[0]), "r"(b[1]));
}
__device__ __forceinline__ void mma16816(float* c, const uint32_t* a, const uint32_t* b) {
    asm volatile(
        "mma.sync.aligned.m16n8k16.row.col.f32.bf16.bf16.f32 "
        "{%0,%1,%2,%3}, {%4,%5,%6,%7}, {%8,%9}, {%0,%1,%2,%3};"
        : "+f"(c[0]), "+f"(c[1]), "+f"(c[2]), "+f"(c[3])
        : "r"(a[0]), "r"(a[1]), "r"(a[2]), "r"(a[3]), "r"(b[0]), "r"(b[1]));
}
__device__ __forceinline__ void ldm_x4(uint32_t* r, uint32_t a) {
    asm volatile("ldmatrix.sync.aligned.m8n8.x4.shared.b16 {%0,%1,%2,%3}, [%4];"
        : "=r"(r[0]), "=r"(r[1]), "=r"(r[2]), "=r"(r[3]) : "r"(a));
}

// ===========================================================================
// bf16x3 GEMM (NT): C = (Ah+Al)(Bh+Bl)^T via al*bh + ah*bl + ah*bh
// BM=BN=128, BK=32 bf16, 3-stage cp.async, single-sync pipeline, 256 thr,
// warp 2m x 4n, 64x32 warp tile; fragments via hoisted ldmatrix.x4.
// MODE 0 supports a TRIPLE merged launch via blockIdx.z (sets 1/2/3).
// MODE 6 is the merged channel-mix launch: blockIdx.x<32 -> Kc (relu^2,
// N=4096, bf16-pair out), else -> R2 (plain fp32 out, N=1024).
// MODEs: 0: Of = acc (+bias1)     1: relu(acc)^2 -> (Oh,Ol)
//        3: sigmoid(ex1)*(acc+bias1+ex2) -> (Oh,Ol)
//        4: Of = ex1 + acc        5: Of = ex1 + sigmoid(ex2)*acc
// ===========================================================================
#define BTILE 8192                    // 128*32*2
#define BSTG  (4 * BTILE)             // 32768
#define BNSTG 3
#define BF_DSMEM (BNSTG * BSTG + 128) // 98432

__device__ __forceinline__ void load_stage_bf(
    uint32_t sbase, int stage,
    const __nv_bfloat16* __restrict__ Ah, const __nv_bfloat16* __restrict__ Al,
    const __nv_bfloat16* __restrict__ Bh, const __nv_bfloat16* __restrict__ Bl,
    int bm, int bn, int k0, int K, int tid)
{
    uint32_t s = sbase + stage * BSTG;
#pragma unroll
    for (int j = 0; j < 2; j++) {
        int gi = tid + j * 256;        // 0..511
        int row = gi >> 2, g = gi & 3;
        uint32_t so = (uint32_t)(row * 64 + ((g ^ ((row >> 1) & 3)) << 4));
        long ao = (long)(bm + row) * K + k0 + g * 8;
        long bo = (long)(bn + row) * K + k0 + g * 8;
        cp16(s + so,             Ah + ao);
        cp16(s + BTILE + so,     Al + ao);
        cp16(s + 2 * BTILE + so, Bh + bo);
        cp16(s + 3 * BTILE + so, Bl + bo);
    }
}

template<int MODE>
__global__ void __launch_bounds__(256, 2) gemm_bf(
    const __nv_bfloat16* __restrict__ Ah, const __nv_bfloat16* __restrict__ Al,
    const __nv_bfloat16* __restrict__ Bh, const __nv_bfloat16* __restrict__ Bl,
    const float* __restrict__ bias1,
    const float* __restrict__ ex1, const float* __restrict__ ex2,
    float* __restrict__ Of,
    __nv_bfloat16* __restrict__ Oh, __nv_bfloat16* __restrict__ Ol,
    int M, int N, int K,
    const __nv_bfloat16* A2h, const __nv_bfloat16* A2l,
    const __nv_bfloat16* B2h, const __nv_bfloat16* B2l, float* Of2,
    const __nv_bfloat16* A3h, const __nv_bfloat16* A3l,
    const __nv_bfloat16* B3h, const __nv_bfloat16* B3l, float* Of3,
    const float* bias3)
{
    extern __shared__ __align__(16) char dsm[];

    bool second = false;   // MODE 6: R2 sub-launch
    int bn;
    if (MODE == 0) {
        if (blockIdx.z == 1) { Ah = A2h; Al = A2l; Bh = B2h; Bl = B2l; Of = Of2; }
        else if (blockIdx.z == 2) {
            Ah = A3h; Al = A3l; Bh = B3h; Bl = B3l; Of = Of3; bias1 = bias3;
        }
        bn = blockIdx.x * 128;
    } else if (MODE == 6) {
        if (blockIdx.x < 32) {
            bn = blockIdx.x * 128;            // Kc path, N stays 4096
        } else {
            second = true;
            Ah = A2h; Al = A2l; Bh = B2h; Bl = B2l;
            N = 1024;
            bn = (blockIdx.x - 32) * 128;     // R2 path
        }
    } else {
        bn = blockIdx.x * 128;
    }

    const int tid  = threadIdx.x;
    const int wid  = tid >> 5;
    const int lane = tid & 31;
    const int wm   = wid & 1;
    const int wn   = wid >> 1;
    const int bm = blockIdx.y * 128;
    const int KT = K / 32;
    const int lr = lane >> 2, lk = lane & 3;

    float acc[4][4][4];
#pragma unroll
    for (int i = 0; i < 4; i++)
#pragma unroll
        for (int j = 0; j < 4; j++)
#pragma unroll
            for (int r = 0; r < 4; r++) acc[i][j][r] = 0.f;

    // ldmatrix per-lane swizzled base offsets (granule bit from lane>>4)
    uint32_t offA[4], offB[2];
    {
        int ga = (lane >> 4) & 1;
        int rb = wm * 64 + (lane & 15);
#pragma unroll
        for (int mf = 0; mf < 4; mf++) {
            int row = rb + mf * 16;
            offA[mf] = (uint32_t)(row * 64 + ((ga ^ ((row >> 1) & 3)) << 4));
        }
#pragma unroll
        for (int pg = 0; pg < 2; pg++) {
            int row = wn * 32 + pg * 16 + (lane & 15);
            offB[pg] = (uint32_t)(row * 64 + ((ga ^ ((row >> 1) & 3)) << 4)) + 2 * BTILE;
        }
    }

    uint32_t sbase = (smem_u32(dsm) + 127u) & ~127u;
    load_stage_bf(sbase, 0, Ah, Al, Bh, Bl, bm, bn, 0, K, tid);
    asm volatile("cp.async.commit_group;" ::: "memory");
    load_stage_bf(sbase, 1, Ah, Al, Bh, Bl, bm, bn, 32, K, tid);
    asm volatile("cp.async.commit_group;" ::: "memory");

    int stage = 0;
    for (int kt = 0; kt < KT; kt++) {
        asm volatile("cp.async.wait_group 1;" ::: "memory");
        __syncthreads();   // also orders kt-1 MMAs before overwriting stage kt+2

        int ps = kt + 2;
        if (ps < KT) {
            int pstage = stage + 2; if (pstage >= BNSTG) pstage -= BNSTG;
            load_stage_bf(sbase, pstage, Ah, Al, Bh, Bl, bm, bn, ps * 32, K, tid);
        }
        asm volatile("cp.async.commit_group;" ::: "memory");

        uint32_t st = sbase + stage * BSTG;

#pragma unroll
        for (int ks = 0; ks < 2; ks++) {
            uint32_t kx = (uint32_t)(ks << 5);
            uint32_t tb0[4], tl0[4], tb1[4], tl1[4];
            ldm_x4(tb0, (st + offB[0]) ^ kx);
            ldm_x4(tl0, (st + offB[0] + BTILE) ^ kx);
            ldm_x4(tb1, (st + offB[1]) ^ kx);
            ldm_x4(tl1, (st + offB[1] + BTILE) ^ kx);
            uint32_t ah[4][4], al[4][4];
#pragma unroll
            for (int mf = 0; mf < 4; mf++) {
                ldm_x4(ah[mf], (st + offA[mf]) ^ kx);
                ldm_x4(al[mf], (st + offA[mf] + BTILE) ^ kx);
            }
            uint32_t b_h[4][2] = {{tb0[0],tb0[2]},{tb0[1],tb0[3]},
                                  {tb1[0],tb1[2]},{tb1[1],tb1[3]}};
            uint32_t b_l[4][2] = {{tl0[0],tl0[2]},{tl0[1],tl0[3]},
                                  {tl1[0],tl1[2]},{tl1[1],tl1[3]}};
#pragma unroll
            for (int mf = 0; mf < 4; mf++)
#pragma unroll
                for (int nf = 0; nf < 4; nf++) {
                    mma16816(acc[mf][nf], al[mf], b_h[nf]);
                    mma16816(acc[mf][nf], ah[mf], b_l[nf]);
                    mma16816(acc[mf][nf], ah[mf], b_h[nf]);
                }
        }
        stage++; if (stage >= BNSTG) stage = 0;
    }

    // epilogue
#pragma unroll
    for (int mf = 0; mf < 4; mf++) {
        int r0 = bm + wm * 64 + mf * 16 + lr;
#pragma unroll
        for (int nf = 0; nf < 4; nf++) {
            int c0 = bn + wn * 32 + nf * 8 + lk * 2;
#pragma unroll
            for (int h = 0; h < 2; h++) {
                int row = r0 + h * 8;
                long idx = (long)row * N + c0;
                float vx = acc[mf][nf][2 * h + 0];
                float vy = acc[mf][nf][2 * h + 1];
                if (MODE == 0) {
                    if (bias1) { vx += bias1[c0]; vy += bias1[c0 + 1]; }
                    *(float2*)(Of + idx) = make_float2(vx, vy);
                } else if (MODE == 1) {
                    vx = fmaxf(vx, 0.f); vx *= vx;
                    vy = fmaxf(vy, 0.f); vy *= vy;
                    bpair_store(Oh, Ol, idx, vx, vy);
                } else if (MODE == 3) {
                    vx += bias1[c0]; vy += bias1[c0 + 1];
                    float rx = sigmoidf_(ex1[idx])     * (vx + ex2[idx]);
                    float ry = sigmoidf_(ex1[idx + 1]) * (vy + ex2[idx + 1]);
                    bpair_store(Oh, Ol, idx, rx, ry);
                } else if (MODE == 4) {
                    *(float2*)(Of + idx) = make_float2(ex1[idx] + vx, ex1[idx + 1] + vy);
                } else if (MODE == 5) {
                    float rx = ex1[idx]     + sigmoidf_(ex2[idx])     * vx;
                    float ry = ex1[idx + 1] + sigmoidf_(ex2[idx + 1]) * vy;
                    *(float2*)(Of + idx) = make_float2(rx, ry);
                } else { // MODE 6
                    if (!second) {
                        vx = fmaxf(vx, 0.f); vx *= vx;
                        vy = fmaxf(vy, 0.f); vy *= vy;
                        bpair_store(Oh, Ol, idx, vx, vy);
                    } else {
                        *(float2*)(Of2 + idx) = make_float2(vx, vy);
                    }
                }
            }
        }
    }
}

// ===========================================================================
// tf32x3 GEMM (NT) with in-kernel split (fp32 inputs) — precision path.
// MODEs: 0: O1 = alpha*acc (batched via blockIdx.z strides)
//        2: QK: col<64 -> Qf=acc+qb, col>=64 -> Kf=acc+kb (fp32 [row][64])
// ===========================================================================
#define TBKF 16
#define T_A_BYTES (128 * TBKF * 4)      // 8192
#define T_STG     (2 * T_A_BYTES)       // 16384
#define TNSTG 4
#define TF_DSMEM (TNSTG * T_STG)        // 65536

__device__ __forceinline__ uint32_t lde(const uint32_t* t, int row, int k) {
    int g = k >> 2;
    return t[row * 16 + (((g ^ ((row >> 1) & 3)) << 2) | (k & 3))];
}

__device__ __forceinline__ void load_stage_tf(
    uint32_t sbase, int stage, const float* __restrict__ A,
    const float* __restrict__ B, int bm, int bn, int k0, int K, int tid)
{
    uint32_t sa = sbase + stage * T_STG;
    uint32_t sb = sa + T_A_BYTES;
    int row = tid >> 1;
    int g0 = (tid & 1) * 2;
#pragma unroll
    for (int j = 0; j < 2; j++) {
        int g = g0 + j;
        uint32_t so = (uint32_t)(row * 64 + ((g ^ ((row >> 1) & 3)) << 4));
        cp16(sa + so, A + (long)(bm + row) * K + k0 + g * 4);
        cp16(sb + so, B + (long)(bn + row) * K + k0 + g * 4);
    }
}

template<int MODE>
__global__ void __launch_bounds__(256) gemm_tf(
    const float* __restrict__ A, const float* __restrict__ B,
    const float* __restrict__ qb, const float* __restrict__ kb,
    float* __restrict__ O1, float* __restrict__ Qf, float* __restrict__ Kf,
    int M, int N, int K, float alpha, long sA, long sB, long sC)
{
    extern __shared__ __align__(16) char dsm[];

    A += (long)blockIdx.z * sA;
    B += (long)blockIdx.z * sB;
    O1 += (long)blockIdx.z * sC;

    const int tid  = threadIdx.x;
    const int wid  = tid >> 5;
    const int lane = tid & 31;
    const int wm   = wid & 1;
    const int wn   = wid >> 1;
    const int bm = blockIdx.y * 128;
    const int bn = blockIdx.x * 128;
    const int KT = K / TBKF;

    uint32_t sbase = smem_u32(dsm);

    float acc[4][4][4];
#pragma unroll
    for (int i = 0; i < 4; i++)
#pragma unroll
        for (int j = 0; j < 4; j++)
#pragma unroll
            for (int r = 0; r < 4; r++) acc[i][j][r] = 0.f;

#pragma unroll
    for (int s = 0; s < TNSTG - 1; s++) {
        if (s < KT) load_stage_tf(sbase, s, A, B, bm, bn, s * TBKF, K, tid);
        asm volatile("cp.async.commit_group;" ::: "memory");
    }

    const int lr = lane >> 2;
    const int lk = lane & 3;

    for (int kt = 0; kt < KT; kt++) {
        __syncthreads();
        if (kt + 3 < KT)
            load_stage_tf(sbase, (kt + 3) & 3, A, B, bm, bn, (kt + 3) * TBKF, K, tid);
        asm volatile("cp.async.commit_group;" ::: "memory");
        asm volatile("cp.async.wait_group 3;" ::: "memory");
        __syncthreads();

        const uint32_t* sa = (const uint32_t*)(dsm + (size_t)(kt & 3) * T_STG);
        const uint32_t* sb = sa + 128 * TBKF;

#pragma unroll
        for (int ks = 0; ks < 2; ks++) {
            int kbase = ks * 8;
            uint32_t ah[4][4], al[4][4], bh[4][2], bl[4][2];
#pragma unroll
            for (int mf = 0; mf < 4; mf++) {
                int r0 = wm * 64 + mf * 16 + lr;
                split_tf32(lde(sa, r0,     kbase + lk),     ah[mf][0], al[mf][0]);
                split_tf32(lde(sa, r0 + 8, kbase + lk),     ah[mf][1], al[mf][1]);
                split_tf32(lde(sa, r0,     kbase + lk + 4), ah[mf][2], al[mf][2]);
                split_tf32(lde(sa, r0 + 8, kbase + lk + 4), ah[mf][3], al[mf][3]);
            }
#pragma unroll
            for (int nf = 0; nf < 4; nf++) {
                int n0 = wn * 32 + nf * 8 + lr;
                split_tf32(lde(sb, n0, kbase + lk),     bh[nf][0], bl[nf][0]);
                split_tf32(lde(sb, n0, kbase + lk + 4), bh[nf][1], bl[nf][1]);
            }
#pragma unroll
            for (int mf = 0; mf < 4; mf++)
#pragma unroll
                for (int nf = 0; nf < 4; nf++) {
                    mma1688(acc[mf][nf], al[mf], bh[nf]);
                    mma1688(acc[mf][nf], ah[mf], bl[nf]);
                    mma1688(acc[mf][nf], ah[mf], bh[nf]);
                }
        }
    }

#pragma unroll
    for (int mf = 0; mf < 4; mf++) {
        int r0 = bm + wm * 64 + mf * 16 + lr;
#pragma unroll
        for (int nf = 0; nf < 4; nf++) {
            int c0 = bn + wn * 32 + nf * 8 + lk * 2;
#pragma unroll
            for (int h = 0; h < 2; h++) {
                int row = r0 + h * 8;
                float vx = acc[mf][nf][2 * h + 0] * alpha;
                float vy = acc[mf][nf][2 * h + 1] * alpha;
                if (MODE == 0) {
                    *(float2*)(O1 + (long)row * N + c0) = make_float2(vx, vy);
                } else { // MODE 2: Q||K
                    if (c0 < 64) {
                        vx += qb[c0]; vy += qb[c0 + 1];
                        *(float2*)(Qf + (long)row * 64 + c0) = make_float2(vx, vy);
                    } else {
                        vx += kb[c0 - 64]; vy += kb[c0 - 63];
                        *(float2*)(Kf + (long)row * 64 + c0 - 64) = make_float2(vx, vy);
                    }
                }
            }
        }
    }
}

// ---------------------------------------------------------------------------
// Weight splits: fp32 -> bf16 hi/lo, one fused launch (8 jobs, guarded)
// ---------------------------------------------------------------------------
struct SplitJob { const float* src; __nv_bfloat16* h; __nv_bfloat16* l; long n; };
struct SplitJobs8 { SplitJob j[8]; };

__global__ void __launch_bounds__(256) split8(SplitJobs8 jobs)
{
    const SplitJob jb = jobs.j[blockIdx.y];
    long i = ((long)blockIdx.x * 256 + threadIdx.x) * 2;
    if (i < jb.n) bpair_store(jb.h, jb.l, i, jb.src[i], jb.src[i + 1]);
}

__global__ void __launch_bounds__(256) concat_qk(
    const float* __restrict__ q, const float* __restrict__ k, float* __restrict__ o)
{
    int i = blockIdx.x * 256 + threadIdx.x;   // n = 131072
    o[i] = (i < 65536) ? q[i] : k[i - 65536];
}

// ---------------------------------------------------------------------------
// Fused RMSNorm + token-shift mixing.
// ---------------------------------------------------------------------------
template<int WRITE_H>
__global__ void __launch_bounds__(256) norm_mix_kernel(
    const float* __restrict__ x, const float* __restrict__ w,
    const float* __restrict__ mA, const float* __restrict__ mB,
    __nv_bfloat16* __restrict__ oAh, __nv_bfloat16* __restrict__ oAl,
    __nv_bfloat16* __restrict__ oBh, __nv_bfloat16* __restrict__ oBl,
    float* __restrict__ hF, __nv_bfloat16* __restrict__ hbH,
    __nv_bfloat16* __restrict__ hbL)
{
    long row = blockIdx.x;
    long prev = ((row & (S_LEN - 1)) == 0) ? row : row - 1;
    int tid = threadIdx.x;
    const float* xc = x + row * D_DIM;
    const float* xp = x + prev * D_DIM;

    float c[4], p[4];
    float sc_ = 0.f, sp_ = 0.f;
#pragma unroll
    for (int d = 0; d < 4; d++) {
        c[d] = xc[tid + d * 256];
        p[d] = xp[tid + d * 256];
        sc_ += c[d] * c[d];
        sp_ += p[d] * p[d];
    }
#pragma unroll
    for (int o = 16; o > 0; o >>= 1) {
        sc_ += __shfl_xor_sync(0xffffffffu, sc_, o);
        sp_ += __shfl_xor_sync(0xffffffffu, sp_, o);
    }

    __shared__ float redc[8], redp[8];
    __shared__ float s_invc, s_invp;
    if ((tid & 31) == 0) { redc[tid >> 5] = sc_; redp[tid >> 5] = sp_; }
    __syncthreads();
    if (tid == 0) {
        float tc = 0.f, tp = 0.f;
#pragma unroll
        for (int i = 0; i < 8; i++) { tc += redc[i]; tp += redp[i]; }
        s_invc = 1.0f / (sqrtf(tc / (float)D_DIM) + 1e-8f);
        s_invp = 1.0f / (sqrtf(tp / (float)D_DIM) + 1e-8f);
    }
    __syncthreads();
    float invc = s_invc, invp = s_invp;

#pragma unroll
    for (int d = 0; d < 4; d++) {
        int cc = tid + d * 256;
        long ci = row * D_DIM + cc;
        float nc = w[cc] * c[d] * invc;
        float np = w[cc] * p[d] * invp;
        float a = mA[cc], b = mB[cc];
        bsplit_store(oAh, oAl, ci, nc * a + np * (1.f - a));
        bsplit_store(oBh, oBl, ci, nc * b + np * (1.f - b));
        if (WRITE_H) {
            hF[ci] = nc;
            bsplit_store(hbH, hbL, ci, nc);
        }
    }
}

// ---------------------------------------------------------------------------
// Sparse attention: chunked top-32, softmax, attn@V -> bf16 pair out.
// ---------------------------------------------------------------------------
__global__ void __launch_bounds__(256) sparse_attn_kernel(
    const float* __restrict__ scores, const float* __restrict__ V,
    __nv_bfloat16* __restrict__ oh, __nv_bfloat16* __restrict__ ol)
{
    __shared__ float sc[S_LEN];
    __shared__ float cmax[128];
    __shared__ float selV[TOPK];
    __shared__ int   selI[TOPK];
    __shared__ float wsel[TOPK];

    long row = blockIdx.x;
    long b = row >> 12;
    int tid = threadIdx.x;
    int lane = tid & 31;

    const float* srow = scores + row * S_LEN;
    for (int i = tid; i < S_LEN; i += 256) sc[i] = srow[i];
    __syncthreads();

    if (tid < 128) {
        float m = NEG_INF;
#pragma unroll 8
        for (int i = 0; i < 32; i++) m = fmaxf(m, sc[tid * 32 + i]);
        cmax[tid] = m;
    }
    __syncthreads();

    if (tid < 32) {
        for (int it = 0; it < TOPK; it++) {
            float bv = NEG_INF; int bc = 0;
#pragma unroll
            for (int j = 0; j < 4; j++) {
                int c = lane * 4 + j;
                float v = cmax[c];
                if (v > bv) { bv = v; bc = c; }
            }
#pragma unroll
            for (int o = 16; o > 0; o >>= 1) {
                float ov = __shfl_down_sync(0xffffffffu, bv, o);
                int   oc = __shfl_down_sync(0xffffffffu, bc, o);
                if (ov > bv || (ov == bv && oc < bc)) { bv = ov; bc = oc; }
            }
            bc = __shfl_sync(0xffffffffu, bc, 0);

            float v = sc[bc * 32 + lane];
            float mv = v; int mi = lane;
#pragma unroll
            for (int o = 16; o > 0; o >>= 1) {
                float ov = __shfl_down_sync(0xffffffffu, mv, o);
                int   oi = __shfl_down_sync(0xffffffffu, mi, o);
                if (ov > mv || (ov == mv && oi < mi)) { mv = ov; mi = oi; }
            }
            mv = __shfl_sync(0xffffffffu, mv, 0);
            mi = __shfl_sync(0xffffffffu, mi, 0);

            if (lane == mi) { sc[bc * 32 + lane] = NEG_INF; v = NEG_INF; }
            if (lane == 0) { selV[it] = mv; selI[it] = bc * 32 + mi; }

            float nm = v;
#pragma unroll
            for (int o = 16; o > 0; o >>= 1)
                nm = fmaxf(nm, __shfl_down_sync(0xffffffffu, nm, o));
            if (lane == 0) cmax[bc] = nm;
        }
        float m = __shfl_sync(0xffffffffu, selV[0], 0);
        float e = expf(selV[lane] - m);
        float s = e;
#pragma unroll
        for (int o = 16; o > 0; o >>= 1) s += __shfl_xor_sync(0xffffffffu, s, o);
        wsel[lane] = e / s;
    }
    __syncthreads();

    float acc[4] = {0.f, 0.f, 0.f, 0.f};
    const float* Vb = V + b * (long)S_LEN * D_DIM;
#pragma unroll 1
    for (int j = 0; j < TOPK; j++) {
        float w = wsel[j];
        const float* vr = Vb + (long)selI[j] * D_DIM;
#pragma unroll
        for (int d = 0; d < 4; d++) acc[d] += w * vr[tid + d * 256];
    }
#pragma unroll
    for (int d = 0; d < 4; d++)
        bsplit_store(oh, ol, row * D_DIM + tid + d * 256, acc[d]);
}

// ---------------------------------------------------------------------------
// Host launchers
// ---------------------------------------------------------------------------
typedef __nv_bfloat16 bf16;

static void launch_bf(int mode,
    const bf16* Ah, const bf16* Al, const bf16* Bh, const bf16* Bl,
    const float* b1, const float* e1, const float* e2,
    float* Of, bf16* Oh, bf16* Ol, int M, int N, int K,
    const bf16* A2h = nullptr, const bf16* A2l = nullptr,
    const bf16* B2h = nullptr, const bf16* B2l = nullptr, float* Of2 = nullptr,
    const bf16* A3h = nullptr, const bf16* A3l = nullptr,
    const bf16* B3h = nullptr, const bf16* B3l = nullptr, float* Of3 = nullptr,
    const float* b3 = nullptr, int gx = -1, int gz = 1)
{
    dim3 grid(gx < 0 ? N / 128 : gx, M / 128, gz);
    switch (mode) {
    case 0: gemm_bf<0><<<grid, 256, BF_DSMEM>>>(Ah,Al,Bh,Bl,b1,e1,e2,Of,Oh,Ol,M,N,K,A2h,A2l,B2h,B2l,Of2,A3h,A3l,B3h,B3l,Of3,b3); break;
    case 1: gemm_bf<1><<<grid, 256, BF_DSMEM>>>(Ah,Al,Bh,Bl,b1,e1,e2,Of,Oh,Ol,M,N,K,A2h,A2l,B2h,B2l,Of2,A3h,A3l,B3h,B3l,Of3,b3); break;
    case 3: gemm_bf<3><<<grid, 256, BF_DSMEM>>>(Ah,Al,Bh,Bl,b1,e1,e2,Of,Oh,Ol,M,N,K,A2h,A2l,B2h,B2l,Of2,A3h,A3l,B3h,B3l,Of3,b3); break;
    case 4: gemm_bf<4><<<grid, 256, BF_DSMEM>>>(Ah,Al,Bh,Bl,b1,e1,e2,Of,Oh,Ol,M,N,K,A2h,A2l,B2h,B2l,Of2,A3h,A3l,B3h,B3l,Of3,b3); break;
    case 5: gemm_bf<5><<<grid, 256, BF_DSMEM>>>(Ah,Al,Bh,Bl,b1,e1,e2,Of,Oh,Ol,M,N,K,A2h,A2l,B2h,B2l,Of2,A3h,A3l,B3h,B3l,Of3,b3); break;
    default: gemm_bf<6><<<grid, 256, BF_DSMEM>>>(Ah,Al,Bh,Bl,b1,e1,e2,Of,Oh,Ol,M,N,K,A2h,A2l,B2h,B2l,Of2,A3h,A3l,B3h,B3l,Of3,b3); break;
    }
}

extern "C" void kernel_launch(void* const* d_in, const int* in_sizes, int n_in,
                              void* d_out, int out_size)
{
    const float* x         = (const float*)d_in[0];
    const float* norm1_w   = (const float*)d_in[1];
    const float* tm_mix_v  = (const float*)d_in[3];
    const float* tm_mix_r  = (const float*)d_in[4];
    const float* tm_value_w  = (const float*)d_in[6];
    const float* tm_recept_w = (const float*)d_in[7];
    const float* tm_out_w    = (const float*)d_in[8];
    const float* sa_q_w    = (const float*)d_in[9];
    const float* sa_q_b    = (const float*)d_in[10];
    const float* sa_k_w    = (const float*)d_in[11];
    const float* sa_k_b    = (const float*)d_in[12];
    const float* sa_v_w    = (const float*)d_in[13];
    const float* sa_v_b    = (const float*)d_in[14];
    const float* sa_o_w    = (const float*)d_in[15];
    const float* sa_o_b    = (const float*)d_in[16];
    const float* norm2_w   = (const float*)d_in[17];
    const float* cm_mix_k  = (const float*)d_in[18];
    const float* cm_mix_r  = (const float*)d_in[19];
    const float* cm_key_w    = (const float*)d_in[20];
    const float* cm_recept_w = (const float*)d_in[21];
    const float* cm_value_w  = (const float*)d_in[22];
    float* out = (float*)d_out;

    cudaFuncSetAttribute(gemm_bf<0>, cudaFuncAttributeMaxDynamicSharedMemorySize, BF_DSMEM);
    cudaFuncSetAttribute(gemm_bf<1>, cudaFuncAttributeMaxDynamicSharedMemorySize, BF_DSMEM);
    cudaFuncSetAttribute(gemm_bf<3>, cudaFuncAttributeMaxDynamicSharedMemorySize, BF_DSMEM);
    cudaFuncSetAttribute(gemm_bf<4>, cudaFuncAttributeMaxDynamicSharedMemorySize, BF_DSMEM);
    cudaFuncSetAttribute(gemm_bf<5>, cudaFuncAttributeMaxDynamicSharedMemorySize, BF_DSMEM);
    cudaFuncSetAttribute(gemm_bf<6>, cudaFuncAttributeMaxDynamicSharedMemorySize, BF_DSMEM);
    cudaFuncSetAttribute(gemm_tf<0>, cudaFuncAttributeMaxDynamicSharedMemorySize, TF_DSMEM);
    cudaFuncSetAttribute(gemm_tf<2>, cudaFuncAttributeMaxDynamicSharedMemorySize, TF_DSMEM);

    float* sp = nullptr;
    cudaGetSymbolAddress((void**)&sp, g_scratch);

    float* hF   = sp + O_HF;
    float* Vtm  = sp + O_VTM;
    float* Rtm  = sp + O_RTM;
    float* Vv   = sp + O_VV;
    float* x2   = sp + O_X2;
    float* R2   = sp + O_R2;
    float* Qf   = sp + O_Q;
    float* Kf   = sp + O_K;
    float* wQKf = sp + O_WQKF;
    float* SCo  = sp + O_SC;

    bf16* hbH = (bf16*)(sp + O_BHB); bf16* hbL = (bf16*)(sp + O_BHL);
    bf16* xvH = (bf16*)(sp + O_XVH); bf16* xvL = (bf16*)(sp + O_XVL);
    bf16* xrH = (bf16*)(sp + O_XRH); bf16* xrL = (bf16*)(sp + O_XRL);
    bf16* atH = (bf16*)(sp + O_ATH); bf16* atL = (bf16*)(sp + O_ATL);
    bf16* rkH = (bf16*)(sp + O_RKH); bf16* rkL = (bf16*)(sp + O_RKL);
    bf16* KcH = (bf16*)(sp + O_KCH); bf16* KcL = (bf16*)(sp + O_KCL);

    bf16* wTMVh = (bf16*)(sp + O_WTMV); bf16* wTMVl = wTMVh + 1048576L;
    bf16* wTMRh = (bf16*)(sp + O_WTMR); bf16* wTMRl = wTMRh + 1048576L;
    bf16* wSAVh = (bf16*)(sp + O_WSAV); bf16* wSAVl = wSAVh + 1048576L;
    bf16* wSAOh = (bf16*)(sp + O_WSAO); bf16* wSAOl = wSAOh + 1048576L;
    bf16* wTMOh = (bf16*)(sp + O_WTMO); bf16* wTMOl = wTMOh + 1048576L;
    bf16* wCMRh = (bf16*)(sp + O_WCMR); bf16* wCMRl = wCMRh + 1048576L;
    bf16* wCMKh = (bf16*)(sp + O_WCMK); bf16* wCMKl = wCMKh + 4194304L;
    bf16* wCMVh = (bf16*)(sp + O_WCMV); bf16* wCMVl = wCMVh + 4194304L;

    // one fused weight-split launch (guarded per-job n) + QK concat
    {
        SplitJobs8 s8;
        s8.j[0] = {tm_value_w,  wTMVh, wTMVl, 1048576L};
        s8.j[1] = {tm_recept_w, wTMRh, wTMRl, 1048576L};
        s8.j[2] = {sa_v_w,      wSAVh, wSAVl, 1048576L};
        s8.j[3] = {sa_o_w,      wSAOh, wSAOl, 1048576L};
        s8.j[4] = {tm_out_w,    wTMOh, wTMOl, 1048576L};
        s8.j[5] = {cm_recept_w, wCMRh, wCMRl, 1048576L};
        s8.j[6] = {cm_key_w,    wCMKh, wCMKl, 4194304L};
        s8.j[7] = {cm_value_w,  wCMVh, wCMVl, 4194304L};
        split8<<<dim3(8192, 8, 1), 256>>>(s8);
        concat_qk<<<512, 256>>>(sa_q_w, sa_k_w, wQKf);
    }

    // --- time-mix branch ---
    norm_mix_kernel<1><<<NROWS, 256>>>(x, norm1_w, tm_mix_v, tm_mix_r,
                                       xvH, xvL, xrH, xrL, hF, hbH, hbL);

    // triple merged GEMM: z=0 Vtm, z=1 Rtm, z=2 Vv (bias sa_v_b)
    launch_bf(0, xvH, xvL, wTMVh, wTMVl, nullptr, nullptr, nullptr,
              Vtm, nullptr, nullptr, NROWS, D_DIM, D_DIM,
              xrH, xrL, wTMRh, wTMRl, Rtm,
              hbH, hbL, wSAVh, wSAVl, Vv, sa_v_b, -1, 3);

    // Q||K projection on tf32x3 precision path
    {
        dim3 g(1, NROWS / 128, 1);
        gemm_tf<2><<<g, 256, TF_DSMEM>>>(hF, wQKf, sa_q_b, sa_k_b,
                                         nullptr, Qf, Kf, NROWS, 128, D_DIM,
                                         1.f, 0, 0, 0);
    }

    // scores[b] = (Q[b] @ K[b]^T) / 8 on tf32x3
    {
        dim3 g(S_LEN / 128, S_LEN / 128, B_SZ);
        gemm_tf<0><<<g, 256, TF_DSMEM>>>(Qf, Kf, nullptr, nullptr,
                                         SCo, nullptr, nullptr, S_LEN, S_LEN, A_DIM,
                                         0.125f, (long)S_LEN * A_DIM,
                                         (long)S_LEN * A_DIM, (long)S_LEN * S_LEN);
    }

    sparse_attn_kernel<<<NROWS, 256>>>(SCo, Vv, atH, atL);

    // rkv = sigmoid(Rtm) * (attn@W_o + b_o + Vtm) -> bf16 pair
    launch_bf(3, atH, atL, wSAOh, wSAOl, sa_o_b, Rtm, Vtm,
              nullptr, rkH, rkL, NROWS, D_DIM, D_DIM);

    // x2 = x + rkv @ W_out
    launch_bf(4, rkH, rkL, wTMOh, wTMOl, nullptr, x, nullptr,
              x2, nullptr, nullptr, NROWS, D_DIM, D_DIM);

    // --- channel-mix branch ---
    norm_mix_kernel<0><<<NROWS, 256>>>(x2, norm2_w, cm_mix_k, cm_mix_r,
                                       xvH, xvL, xrH, xrL,
                                       nullptr, nullptr, nullptr);

    // merged: blocks x<32 -> Kc = relu(xk2@W_k)^2 (bf16 pair), x>=32 -> R2
    launch_bf(6, xvH, xvL, wCMKh, wCMKl, nullptr, nullptr, nullptr,
              nullptr, KcH, KcL, NROWS, DI_DIM, D_DIM,
              xrH, xrL, wCMRh, wCMRl, R2,
              nullptr, nullptr, nullptr, nullptr, nullptr, nullptr, 40, 1);

    // out = x2 + sigmoid(R2) * (Kc @ W_v)
    launch_bf(5, KcH, KcL, wCMVh, wCMVl, nullptr, x2, R2,
              out, nullptr, nullptr, NROWS, D_DIM, DI_DIM);
}